// round 4
// baseline (speedup 1.0000x reference)
#include <cuda_runtime.h>

#define V_NODES 50000
#define FEAT    512          // B * Cin
#define CIN     128
#define COUT    128
#define BATCH   4
#define MROWS   (V_NODES * BATCH)   // 200000
#define MAXE    800000
#define KORD    5

// ---------------- static device scratch (no allocations allowed) ----------------
__device__ float g_b0[(size_t)V_NODES * FEAT];
__device__ float g_b1[(size_t)V_NODES * FEAT];
__device__ float g_b2[(size_t)V_NODES * FEAT];
__device__ float g_acc[(size_t)MROWS * COUT];
__device__ int   g_rp[V_NODES + 1];
__device__ int   g_cnt[V_NODES];
__device__ int   g_ccol[MAXE];
__device__ float g_cval[MAXE];

__device__ __forceinline__ float* pick(int i) {
    return i == 0 ? g_b0 : (i == 1 ? g_b1 : g_b2);
}

// ---------------- transpose: x (512, V) -> g_b0 (V, 512) ----------------
__global__ void transpose_in(const float* __restrict__ x) {
    __shared__ float tile[32][33];
    int v = blockIdx.x * 32 + threadIdx.x;
    int f = blockIdx.y * 32 + threadIdx.y;
    if (v < V_NODES)
        tile[threadIdx.y][threadIdx.x] = x[(size_t)f * V_NODES + v];
    __syncthreads();
    int vo = blockIdx.x * 32 + threadIdx.y;
    int fo = blockIdx.y * 32 + threadIdx.x;
    if (vo < V_NODES)
        g_b0[(size_t)vo * FEAT + fo] = tile[threadIdx.x][threadIdx.y];
}

// ---------------- output: g_acc (V,512) -> out (512, V) + bias ----------------
// out[f*V + v] = g_acc[v*512 + f] + bias[f & 127]
// load coalesced over f (contiguous in g_acc), store coalesced over v.
__global__ void write_out(float* __restrict__ out, const float* __restrict__ bias) {
    __shared__ float tile[32][33];
    int tx = threadIdx.x, ty = threadIdx.y;
    int v0 = blockIdx.x * 32, f0 = blockIdx.y * 32;

    int v = v0 + ty;
    int f = f0 + tx;
    if (v < V_NODES)
        tile[ty][tx] = g_acc[(size_t)v * FEAT + f];
    __syncthreads();

    int vo = v0 + tx;
    int fo = f0 + ty;
    if (vo < V_NODES)
        out[(size_t)fo * V_NODES + vo] = tile[tx][ty] + bias[fo & 127];
}

// ---------------- CSR build ----------------
__global__ void zero_cnt() {
    int i = blockIdx.x * blockDim.x + threadIdx.x;
    if (i < V_NODES) g_cnt[i] = 0;
}

__global__ void count_k(const int* __restrict__ rows, int E) {
    int e = blockIdx.x * blockDim.x + threadIdx.x;
    int stride = gridDim.x * blockDim.x;
    for (; e < E; e += stride) atomicAdd(&g_cnt[rows[e]], 1);
}

__global__ void scan_k() {
    __shared__ int sh[1024];
    int t = threadIdx.x;
    const int CH = (V_NODES + 1023) / 1024;   // 49
    int s0 = t * CH;
    int s1 = s0 + CH; if (s1 > V_NODES) s1 = V_NODES;
    int s = 0;
    for (int i = s0; i < s1 && i < V_NODES; i++) s += g_cnt[i];
    sh[t] = s;
    __syncthreads();
    for (int off = 1; off < 1024; off <<= 1) {
        int v = sh[t];
        int add = (t >= off) ? sh[t - off] : 0;
        __syncthreads();
        sh[t] = v + add;
        __syncthreads();
    }
    int run = (t == 0) ? 0 : sh[t - 1];
    for (int i = s0; i < s1 && i < V_NODES; i++) { g_rp[i] = run; run += g_cnt[i]; }
    if (t == 1023) g_rp[V_NODES] = sh[1023];
}

__global__ void scatter_k(const int* __restrict__ rows, const int* __restrict__ cols,
                          const float* __restrict__ vals, int E) {
    int e = blockIdx.x * blockDim.x + threadIdx.x;
    int stride = gridDim.x * blockDim.x;
    for (; e < E; e += stride) {
        int r = rows[e];
        int p = g_rp[r] + atomicAdd(&g_cnt[r], 1);
        g_ccol[p] = cols[e];
        g_cval[p] = vals[e];
    }
}

// ---------------- SpMM: y[v,:] = a * sum_e val*x[col,:]  (+ b * z[v,:]) ----------------
// one warp per row, 512-wide row held as 4 x float4 per lane, no atomics
__global__ void spmm_k(int yi, int xi, int zi, float a, float b, int use_z) {
    int w = (blockIdx.x * blockDim.x + threadIdx.x) >> 5;
    if (w >= V_NODES) return;
    int lane = threadIdx.x & 31;

    const float* __restrict__ x = pick(xi);
    float* __restrict__ y = pick(yi);

    float4 acc[4];
    if (use_z) {
        const float4* z4 = (const float4*)(pick(zi) + (size_t)w * FEAT);
#pragma unroll
        for (int j = 0; j < 4; j++) {
            float4 t = z4[lane + 32 * j];
            acc[j] = make_float4(b * t.x, b * t.y, b * t.z, b * t.w);
        }
    } else {
#pragma unroll
        for (int j = 0; j < 4; j++) acc[j] = make_float4(0.f, 0.f, 0.f, 0.f);
    }

    int p0 = g_rp[w], p1 = g_rp[w + 1];
    for (int p = p0; p < p1; p++) {
        int   c   = g_ccol[p];
        float val = a * g_cval[p];
        const float4* xr = (const float4*)(x + (size_t)c * FEAT);
#pragma unroll
        for (int j = 0; j < 4; j++) {
            float4 xv = xr[lane + 32 * j];
            acc[j].x += val * xv.x;
            acc[j].y += val * xv.y;
            acc[j].z += val * xv.z;
            acc[j].w += val * xv.w;
        }
    }

    float4* y4 = (float4*)(y + (size_t)w * FEAT);
#pragma unroll
    for (int j = 0; j < 4; j++) y4[lane + 32 * j] = acc[j];
}

// ---------------- GEMM accumulate: g_acc (+)= x(200000,128) @ W(128,128) ----------------
// block: 256 threads, tile 64 rows x 128 cols. W + x^T staged in shared.
// x-reads are warp-broadcast (conflict-free); W-reads are float4 across lanes.
__global__ void gemm_k(const float* __restrict__ w, int xi, int accumulate) {
    extern __shared__ float sh[];
    float* ws = sh;             // 128*128 = 16384 floats
    float* xs = sh + 16384;     // 128 * 65 = 8320 floats (xT, padded)

    const float* __restrict__ x = pick(xi);
    int tid = threadIdx.x;
    size_t row0 = (size_t)blockIdx.x * 64;

    float4* ws4 = (float4*)ws;
    const float4* wg = (const float4*)w;
#pragma unroll 4
    for (int i = tid; i < 4096; i += 256) ws4[i] = wg[i];
#pragma unroll 4
    for (int i = tid; i < 8192; i += 256) {
        int r = i >> 7, c = i & 127;
        xs[c * 65 + r] = x[(row0 + r) * 128 + c];
    }
    __syncthreads();

    int wid = tid >> 5, lane = tid & 31;
    int rb = wid * 8;

    float4 a[8];
    float4* accg = (float4*)g_acc;
    if (accumulate) {
#pragma unroll
        for (int i = 0; i < 8; i++) a[i] = accg[(row0 + rb + i) * 32 + lane];
    } else {
#pragma unroll
        for (int i = 0; i < 8; i++) a[i] = make_float4(0.f, 0.f, 0.f, 0.f);
    }

#pragma unroll 4
    for (int c = 0; c < 128; c++) {
        float4 wv = ws4[c * 32 + lane];
#pragma unroll
        for (int i = 0; i < 8; i++) {
            float xv = xs[c * 65 + rb + i];
            a[i].x += xv * wv.x;
            a[i].y += xv * wv.y;
            a[i].z += xv * wv.z;
            a[i].w += xv * wv.w;
        }
    }

#pragma unroll
    for (int i = 0; i < 8; i++) accg[(row0 + rb + i) * 32 + lane] = a[i];
}

// ---------------- launch ----------------
extern "C" void kernel_launch(void* const* d_in, const int* in_sizes, int n_in,
                              void* d_out, int out_size) {
    const float* x        = (const float*)d_in[0];
    const float* lap_vals = (const float*)d_in[1];
    const float* weight   = (const float*)d_in[2];
    const float* bias     = (const float*)d_in[3];
    const int*   rows     = (const int*)d_in[4];
    const int*   cols     = (const int*)d_in[5];
    int E = in_sizes[1];
    float* out = (float*)d_out;

    const int smem = (16384 + 8320) * 4;   // 98816 B
    cudaFuncSetAttribute(gemm_k, cudaFuncAttributeMaxDynamicSharedMemorySize, smem);

    dim3 tb(32, 32);
    dim3 tg((V_NODES + 31) / 32, FEAT / 32);

    // layout in
    transpose_in<<<tg, tb>>>(x);

    // CSR build (fresh every launch; deterministic work)
    zero_cnt<<<(V_NODES + 255) / 256, 256>>>();
    count_k<<<1024, 256>>>(rows, E);
    scan_k<<<1, 1024>>>();
    zero_cnt<<<(V_NODES + 255) / 256, 256>>>();
    scatter_k<<<1024, 256>>>(rows, cols, lap_vals, E);

    // k = 0
    gemm_k<<<MROWS / 64, 256, smem>>>(weight, 0, 0);

    // k = 1 : x1 = L x0
    spmm_k<<<(V_NODES * 32 + 255) / 256, 256>>>(1, 0, 0, 1.0f, 0.0f, 0);
    gemm_k<<<MROWS / 64, 256, smem>>>(weight + 1 * CIN * COUT, 1, 1);

    // k = 2..4 : x2 = 2 L x1 - x0, rotate buffers
    int i0 = 0, i1 = 1, i2 = 2;
    for (int k = 2; k < KORD; k++) {
        spmm_k<<<(V_NODES * 32 + 255) / 256, 256>>>(i2, i1, i0, 2.0f, -1.0f, 1);
        gemm_k<<<MROWS / 64, 256, smem>>>(weight + k * CIN * COUT, i2, 1);
        int t = i0; i0 = i1; i1 = i2; i2 = t;
    }

    // layout out + bias
    write_out<<<tg, tb>>>(out, bias);
}

// round 5
// speedup vs baseline: 1.2937x; 1.2937x over previous
#include <cuda_runtime.h>
#include <cstdint>

#define V_NODES 50000
#define FEAT    512          // B * Cin
#define CIN     128
#define COUT    128
#define BATCH   4
#define MROWS   (V_NODES * BATCH)   // 200000
#define MAXE    800000
#define KORD    5
#define NB_SCAN ((V_NODES + 255) / 256)   // 196

// ---------------- static device scratch (no allocations allowed) ----------------
__device__ float g_b0[(size_t)V_NODES * FEAT];
__device__ float g_b1[(size_t)V_NODES * FEAT];
__device__ float g_b2[(size_t)V_NODES * FEAT];
__device__ float g_b3[(size_t)V_NODES * FEAT];
__device__ float g_b4[(size_t)V_NODES * FEAT];
__device__ float g_acc[(size_t)MROWS * COUT];
__device__ int   g_rp[V_NODES + 1];
__device__ int   g_cnt[V_NODES];
__device__ int   g_bsum[NB_SCAN];
__device__ int   g_boff[NB_SCAN];
__device__ int   g_ccol[MAXE];
__device__ float g_cval[MAXE];

__device__ __forceinline__ float* pick(int i) {
    switch (i) {
        case 0: return g_b0;
        case 1: return g_b1;
        case 2: return g_b2;
        case 3: return g_b3;
        default: return g_b4;
    }
}

// ---------------- tf32 helpers ----------------
__device__ __forceinline__ uint32_t f2tf32(float f) {
    uint32_t r;
    asm("cvt.rna.tf32.f32 %0, %1;" : "=r"(r) : "f"(f));
    return r;
}

__device__ __forceinline__ void mma_tf32(float* d, const uint32_t* a, const uint32_t* b) {
    asm volatile(
        "mma.sync.aligned.m16n8k8.row.col.f32.tf32.tf32.f32 "
        "{%0,%1,%2,%3}, {%4,%5,%6,%7}, {%8,%9}, {%0,%1,%2,%3};"
        : "+f"(d[0]), "+f"(d[1]), "+f"(d[2]), "+f"(d[3])
        : "r"(a[0]), "r"(a[1]), "r"(a[2]), "r"(a[3]), "r"(b[0]), "r"(b[1]));
}

// ---------------- transpose: x (512, V) -> g_b0 (V, 512) ----------------
__global__ void transpose_in(const float* __restrict__ x) {
    __shared__ float tile[32][33];
    int v = blockIdx.x * 32 + threadIdx.x;
    int f = blockIdx.y * 32 + threadIdx.y;
    if (v < V_NODES)
        tile[threadIdx.y][threadIdx.x] = x[(size_t)f * V_NODES + v];
    __syncthreads();
    int vo = blockIdx.x * 32 + threadIdx.y;
    int fo = blockIdx.y * 32 + threadIdx.x;
    if (vo < V_NODES)
        g_b0[(size_t)vo * FEAT + fo] = tile[threadIdx.x][threadIdx.y];
}

// ---------------- output: g_acc (V,512) -> out (512, V) + bias ----------------
__global__ void write_out(float* __restrict__ out, const float* __restrict__ bias) {
    __shared__ float tile[32][33];
    int tx = threadIdx.x, ty = threadIdx.y;
    int v0 = blockIdx.x * 32, f0 = blockIdx.y * 32;

    int v = v0 + ty;
    int f = f0 + tx;
    if (v < V_NODES)
        tile[ty][tx] = g_acc[(size_t)v * FEAT + f];
    __syncthreads();

    int vo = v0 + tx;
    int fo = f0 + ty;
    if (vo < V_NODES)
        out[(size_t)fo * V_NODES + vo] = tile[tx][ty] + bias[fo & 127];
}

// ---------------- CSR build ----------------
__global__ void zero_cnt() {
    int i = blockIdx.x * blockDim.x + threadIdx.x;
    if (i < V_NODES) g_cnt[i] = 0;
}

__global__ void count_k(const int* __restrict__ rows, int E) {
    int e = blockIdx.x * blockDim.x + threadIdx.x;
    int stride = gridDim.x * blockDim.x;
    for (; e < E; e += stride) atomicAdd(&g_cnt[rows[e]], 1);
}

// partial sums per 256-row block
__global__ void scan1_k() {
    __shared__ int sh[256];
    int t = threadIdx.x;
    int i = blockIdx.x * 256 + t;
    int c = (i < V_NODES) ? g_cnt[i] : 0;
    sh[t] = c;
    __syncthreads();
    for (int off = 1; off < 256; off <<= 1) {
        int v = sh[t];
        int add = (t >= off) ? sh[t - off] : 0;
        __syncthreads();
        sh[t] = v + add;
        __syncthreads();
    }
    if (t == 255) g_bsum[blockIdx.x] = sh[255];
}

// scan the NB_SCAN block sums (single block)
__global__ void scan2_k() {
    __shared__ int sh[256];
    int t = threadIdx.x;
    int v0 = (t < NB_SCAN) ? g_bsum[t] : 0;
    sh[t] = v0;
    __syncthreads();
    for (int off = 1; off < 256; off <<= 1) {
        int v = sh[t];
        int add = (t >= off) ? sh[t - off] : 0;
        __syncthreads();
        sh[t] = v + add;
        __syncthreads();
    }
    if (t < NB_SCAN) g_boff[t] = (t == 0) ? 0 : sh[t - 1];
    if (t == NB_SCAN - 1) g_rp[V_NODES] = sh[t];
}

// expand: g_rp[i] = exclusive prefix
__global__ void scan3_k() {
    __shared__ int sh[256];
    int t = threadIdx.x;
    int i = blockIdx.x * 256 + t;
    int c = (i < V_NODES) ? g_cnt[i] : 0;
    sh[t] = c;
    __syncthreads();
    for (int off = 1; off < 256; off <<= 1) {
        int v = sh[t];
        int add = (t >= off) ? sh[t - off] : 0;
        __syncthreads();
        sh[t] = v + add;
        __syncthreads();
    }
    if (i < V_NODES) g_rp[i] = g_boff[blockIdx.x] + sh[t] - c;
}

__global__ void scatter_k(const int* __restrict__ rows, const int* __restrict__ cols,
                          const float* __restrict__ vals, int E) {
    int e = blockIdx.x * blockDim.x + threadIdx.x;
    int stride = gridDim.x * blockDim.x;
    for (; e < E; e += stride) {
        int r = rows[e];
        int p = g_rp[r] + atomicAdd(&g_cnt[r], 1);
        g_ccol[p] = cols[e];
        g_cval[p] = vals[e];
    }
}

// ---------------- SpMM: y[v,:] = a * sum_e val*x[col,:]  (+ b * z[v,:]) ----------------
__global__ void spmm_k(int yi, int xi, int zi, float a, float b, int use_z) {
    int w = (blockIdx.x * blockDim.x + threadIdx.x) >> 5;
    if (w >= V_NODES) return;
    int lane = threadIdx.x & 31;

    const float* __restrict__ x = pick(xi);
    float* __restrict__ y = pick(yi);

    float4 acc[4];
    if (use_z) {
        const float4* z4 = (const float4*)(pick(zi) + (size_t)w * FEAT);
#pragma unroll
        for (int j = 0; j < 4; j++) {
            float4 t = z4[lane + 32 * j];
            acc[j] = make_float4(b * t.x, b * t.y, b * t.z, b * t.w);
        }
    } else {
#pragma unroll
        for (int j = 0; j < 4; j++) acc[j] = make_float4(0.f, 0.f, 0.f, 0.f);
    }

    int p0 = g_rp[w], p1 = g_rp[w + 1];
    for (int p = p0; p < p1; p++) {
        int   c   = g_ccol[p];
        float val = a * g_cval[p];
        const float4* xr = (const float4*)(x + (size_t)c * FEAT);
#pragma unroll
        for (int j = 0; j < 4; j++) {
            float4 xv = xr[lane + 32 * j];
            acc[j].x += val * xv.x;
            acc[j].y += val * xv.y;
            acc[j].z += val * xv.z;
            acc[j].w += val * xv.w;
        }
    }

    float4* y4 = (float4*)(y + (size_t)w * FEAT);
#pragma unroll
    for (int j = 0; j < 4; j++) y4[lane + 32 * j] = acc[j];
}

// ---------------- fused 3xTF32 GEMM: g_acc = X(200000,640) @ W(640,128) ----------------
// X columns kk*128+i live in buffer pick(kk) at (row m, col i): note m*128 == v*512+b*128.
// Block: 256 threads (8 warps, 4x2), tile M=128, N=128 (full N). K-step 32.
// A smem stride 36 (frag LDS banks 4g+tig: conflict-free),
// B smem stride 136 (frag LDS banks 8*tig+g: conflict-free).
#define A_STRIDE 36
#define B_STRIDE 136
#define GEMM_SMEM ((2 * 128 * A_STRIDE + 2 * 32 * B_STRIDE) * 4)   // 71680 B

__global__ __launch_bounds__(256, 2) void gemm3_k(const float* __restrict__ weight) {
    extern __shared__ float sh[];
    float* Ah = sh;                          // 128 x 36
    float* Al = Ah + 128 * A_STRIDE;
    float* Bh = Al + 128 * A_STRIDE;         // 32 x 136
    float* Bl = Bh + 32 * B_STRIDE;

    int tid = threadIdx.x;
    int warp = tid >> 5, lane = tid & 31;
    int g = lane >> 2, tig = lane & 3;
    int wm = warp >> 1, wn = warp & 1;       // 4 x 2 warp grid
    int m_warp = wm * 32, n_warp = wn * 64;
    size_t row0 = (size_t)blockIdx.x * 128;

    float acc[2][8][4];
#pragma unroll
    for (int mt = 0; mt < 2; mt++)
#pragma unroll
        for (int nt = 0; nt < 8; nt++)
#pragma unroll
            for (int j = 0; j < 4; j++) acc[mt][nt][j] = 0.f;

    for (int kb = 0; kb < 20; kb++) {
        int kk  = kb >> 2;             // chebyshev buffer
        int ks0 = (kb & 3) * 32;       // column offset within 128
        const float* A = pick(kk);
        const float* W = weight + kk * (CIN * COUT);

        __syncthreads();   // previous iteration's reads done

        // A tile: 128 rows x 32 cols -> hi/lo smem
#pragma unroll
        for (int q = 0; q < 4; q++) {
            int i = tid + 256 * q;       // 0..1023 float4s
            int r = i >> 3, cg = i & 7;
            size_t ar = row0 + r;
            if (ar >= MROWS) ar = MROWS - 1;
            float4 v = *(const float4*)(A + ar * 128 + ks0 + cg * 4);
            float* dh = Ah + r * A_STRIDE + cg * 4;
            float* dl = Al + r * A_STRIDE + cg * 4;
            float vv[4] = {v.x, v.y, v.z, v.w};
#pragma unroll
            for (int j = 0; j < 4; j++) {
                uint32_t hb = f2tf32(vv[j]);
                float hf = __uint_as_float(hb);
                dh[j] = hf;
                dl[j] = __uint_as_float(f2tf32(vv[j] - hf));
            }
        }

        // B tile: 32 rows x 128 cols -> hi/lo smem
#pragma unroll
        for (int q = 0; q < 4; q++) {
            int i = tid + 256 * q;
            int r = i >> 5, cg = i & 31;
            float4 v = *(const float4*)(W + (ks0 + r) * 128 + cg * 4);
            float* dh = Bh + r * B_STRIDE + cg * 4;
            float* dl = Bl + r * B_STRIDE + cg * 4;
            float vv[4] = {v.x, v.y, v.z, v.w};
#pragma unroll
            for (int j = 0; j < 4; j++) {
                uint32_t hb = f2tf32(vv[j]);
                float hf = __uint_as_float(hb);
                dh[j] = hf;
                dl[j] = __uint_as_float(f2tf32(vv[j] - hf));
            }
        }
        __syncthreads();

#pragma unroll
        for (int ks = 0; ks < 4; ks++) {
            int k0 = ks * 8;
            uint32_t ah[2][4], al[2][4];
#pragma unroll
            for (int mt = 0; mt < 2; mt++) {
                int rb = m_warp + mt * 16;
                ah[mt][0] = __float_as_uint(Ah[(rb + g) * A_STRIDE + k0 + tig]);
                ah[mt][1] = __float_as_uint(Ah[(rb + g + 8) * A_STRIDE + k0 + tig]);
                ah[mt][2] = __float_as_uint(Ah[(rb + g) * A_STRIDE + k0 + tig + 4]);
                ah[mt][3] = __float_as_uint(Ah[(rb + g + 8) * A_STRIDE + k0 + tig + 4]);
                al[mt][0] = __float_as_uint(Al[(rb + g) * A_STRIDE + k0 + tig]);
                al[mt][1] = __float_as_uint(Al[(rb + g + 8) * A_STRIDE + k0 + tig]);
                al[mt][2] = __float_as_uint(Al[(rb + g) * A_STRIDE + k0 + tig + 4]);
                al[mt][3] = __float_as_uint(Al[(rb + g + 8) * A_STRIDE + k0 + tig + 4]);
            }
#pragma unroll
            for (int nt = 0; nt < 8; nt++) {
                int nb = n_warp + nt * 8;
                uint32_t bh[2], bl[2];
                bh[0] = __float_as_uint(Bh[(k0 + tig) * B_STRIDE + nb + g]);
                bh[1] = __float_as_uint(Bh[(k0 + tig + 4) * B_STRIDE + nb + g]);
                bl[0] = __float_as_uint(Bl[(k0 + tig) * B_STRIDE + nb + g]);
                bl[1] = __float_as_uint(Bl[(k0 + tig + 4) * B_STRIDE + nb + g]);
#pragma unroll
                for (int mt = 0; mt < 2; mt++) {
                    mma_tf32(acc[mt][nt], al[mt], bh);   // lo*hi
                    mma_tf32(acc[mt][nt], ah[mt], bl);   // hi*lo
                    mma_tf32(acc[mt][nt], ah[mt], bh);   // hi*hi
                }
            }
        }
    }

    // epilogue -> g_acc (fp32)
#pragma unroll
    for (int mt = 0; mt < 2; mt++) {
#pragma unroll
        for (int nt = 0; nt < 8; nt++) {
            size_t r0 = row0 + m_warp + mt * 16 + g;
            size_t r1 = r0 + 8;
            int c = n_warp + nt * 8 + 2 * tig;
            if (r0 < MROWS)
                *(float2*)(g_acc + r0 * 128 + c) = make_float2(acc[mt][nt][0], acc[mt][nt][1]);
            if (r1 < MROWS)
                *(float2*)(g_acc + r1 * 128 + c) = make_float2(acc[mt][nt][2], acc[mt][nt][3]);
        }
    }
}

// ---------------- launch ----------------
extern "C" void kernel_launch(void* const* d_in, const int* in_sizes, int n_in,
                              void* d_out, int out_size) {
    const float* x        = (const float*)d_in[0];
    const float* lap_vals = (const float*)d_in[1];
    const float* weight   = (const float*)d_in[2];
    const float* bias     = (const float*)d_in[3];
    const int*   rows     = (const int*)d_in[4];
    const int*   cols     = (const int*)d_in[5];
    int E = in_sizes[1];
    float* out = (float*)d_out;

    cudaFuncSetAttribute(gemm3_k, cudaFuncAttributeMaxDynamicSharedMemorySize, GEMM_SMEM);

    dim3 tb(32, 32);
    dim3 tg((V_NODES + 31) / 32, FEAT / 32);

    // layout in: T0
    transpose_in<<<tg, tb>>>(x);

    // CSR build
    zero_cnt<<<(V_NODES + 255) / 256, 256>>>();
    count_k<<<1024, 256>>>(rows, E);
    scan1_k<<<NB_SCAN, 256>>>();
    scan2_k<<<1, 256>>>();
    scan3_k<<<NB_SCAN, 256>>>();
    zero_cnt<<<(V_NODES + 255) / 256, 256>>>();
    scatter_k<<<1024, 256>>>(rows, cols, lap_vals, E);

    // Chebyshev recurrence: T1..T4
    int spgrid = (V_NODES * 32 + 255) / 256;
    spmm_k<<<spgrid, 256>>>(1, 0, 0, 1.0f,  0.0f, 0);   // T1 = L T0
    spmm_k<<<spgrid, 256>>>(2, 1, 0, 2.0f, -1.0f, 1);   // T2 = 2 L T1 - T0
    spmm_k<<<spgrid, 256>>>(3, 2, 1, 2.0f, -1.0f, 1);   // T3 = 2 L T2 - T1
    spmm_k<<<spgrid, 256>>>(4, 3, 2, 2.0f, -1.0f, 1);   // T4 = 2 L T3 - T2

    // fused projection: g_acc = [T0..T4] @ [W0..W4]
    gemm3_k<<<(MROWS + 127) / 128, 256, GEMM_SMEM>>>(weight);

    // layout out + bias
    write_out<<<tg, tb>>>(out, bias);
}

// round 6
// speedup vs baseline: 1.3692x; 1.0584x over previous
#include <cuda_runtime.h>
#include <cstdint>

#define V_NODES 50000
#define FEAT    512          // B * Cin
#define CIN     128
#define COUT    128
#define BATCH   4
#define MROWS   (V_NODES * BATCH)   // 200000
#define MAXE    800000
#define KORD    5
#define NB_SCAN ((V_NODES + 255) / 256)   // 196
#define NCHUNK  4                          // 4 x 128-feature slices

// ---------------- static device scratch (no allocations allowed) ----------------
__device__ float g_b0[(size_t)V_NODES * FEAT];
__device__ float g_b1[(size_t)V_NODES * FEAT];
__device__ float g_b2[(size_t)V_NODES * FEAT];
__device__ float g_b3[(size_t)V_NODES * FEAT];
__device__ float g_b4[(size_t)V_NODES * FEAT];
__device__ float g_acc[(size_t)MROWS * COUT];
__device__ float g_wc[KORD * CIN * COUT];   // combined weights
__device__ int   g_rp[V_NODES + 1];
__device__ int   g_cnt[V_NODES];
__device__ int   g_bsum[NB_SCAN];
__device__ int   g_boff[NB_SCAN];
__device__ int   g_ccol[MAXE];
__device__ float g_cval[MAXE];

__device__ __forceinline__ float* pick(int i) {
    switch (i) {
        case 0: return g_b0;
        case 1: return g_b1;
        case 2: return g_b2;
        case 3: return g_b3;
        default: return g_b4;
    }
}

// ---------------- tf32 helpers ----------------
__device__ __forceinline__ uint32_t f2tf32(float f) {
    uint32_t r;
    asm("cvt.rna.tf32.f32 %0, %1;" : "=r"(r) : "f"(f));
    return r;
}

__device__ __forceinline__ void mma_tf32(float* d, const uint32_t* a, const uint32_t* b) {
    asm volatile(
        "mma.sync.aligned.m16n8k8.row.col.f32.tf32.tf32.f32 "
        "{%0,%1,%2,%3}, {%4,%5,%6,%7}, {%8,%9}, {%0,%1,%2,%3};"
        : "+f"(d[0]), "+f"(d[1]), "+f"(d[2]), "+f"(d[3])
        : "r"(a[0]), "r"(a[1]), "r"(a[2]), "r"(a[3]), "r"(b[0]), "r"(b[1]));
}

// ---------------- transpose: x (512, V) -> g_b0 (V, 512) ----------------
__global__ void transpose_in(const float* __restrict__ x) {
    __shared__ float tile[32][33];
    int v = blockIdx.x * 32 + threadIdx.x;
    int f = blockIdx.y * 32 + threadIdx.y;
    if (v < V_NODES)
        tile[threadIdx.y][threadIdx.x] = x[(size_t)f * V_NODES + v];
    __syncthreads();
    int vo = blockIdx.x * 32 + threadIdx.y;
    int fo = blockIdx.y * 32 + threadIdx.x;
    if (vo < V_NODES)
        g_b0[(size_t)vo * FEAT + fo] = tile[threadIdx.x][threadIdx.y];
}

// ---------------- output: g_acc (V,512) -> out (512, V) + bias ----------------
__global__ void write_out(float* __restrict__ out, const float* __restrict__ bias) {
    __shared__ float tile[32][33];
    int tx = threadIdx.x, ty = threadIdx.y;
    int v0 = blockIdx.x * 32, f0 = blockIdx.y * 32;

    int v = v0 + ty;
    int f = f0 + tx;
    if (v < V_NODES)
        tile[ty][tx] = g_acc[(size_t)v * FEAT + f];
    __syncthreads();

    int vo = v0 + tx;
    int fo = f0 + ty;
    if (vo < V_NODES)
        out[(size_t)fo * V_NODES + vo] = tile[tx][ty] + bias[fo & 127];
}

// ---------------- combined weights ----------------
// T0..T4 = {P0, P1, 2P2-P0, 4P3-3P1, 8P4-8P2+P0};  out = sum_k Tk Wk = sum_j Pj W~j
__global__ void wcomb_k(const float* __restrict__ w) {
    int i = blockIdx.x * 256 + threadIdx.x;
    if (i >= CIN * COUT) return;
    const int S = CIN * COUT;
    float w0 = w[i], w1 = w[i + S], w2 = w[i + 2 * S], w3 = w[i + 3 * S], w4 = w[i + 4 * S];
    g_wc[i]         = w0 - w2 + w4;
    g_wc[i + S]     = w1 - 3.f * w3;
    g_wc[i + 2 * S] = 2.f * w2 - 8.f * w4;
    g_wc[i + 3 * S] = 4.f * w3;
    g_wc[i + 4 * S] = 8.f * w4;
}

// ---------------- CSR build ----------------
__global__ void zero_cnt() {
    int i = blockIdx.x * blockDim.x + threadIdx.x;
    if (i < V_NODES) g_cnt[i] = 0;
}

__global__ void count_k(const int* __restrict__ rows, int E) {
    int e = blockIdx.x * blockDim.x + threadIdx.x;
    int stride = gridDim.x * blockDim.x;
    for (; e < E; e += stride) atomicAdd(&g_cnt[rows[e]], 1);
}

__global__ void scan1_k() {
    __shared__ int sh[256];
    int t = threadIdx.x;
    int i = blockIdx.x * 256 + t;
    int c = (i < V_NODES) ? g_cnt[i] : 0;
    sh[t] = c;
    __syncthreads();
    for (int off = 1; off < 256; off <<= 1) {
        int v = sh[t];
        int add = (t >= off) ? sh[t - off] : 0;
        __syncthreads();
        sh[t] = v + add;
        __syncthreads();
    }
    if (t == 255) g_bsum[blockIdx.x] = sh[255];
}

__global__ void scan2_k() {
    __shared__ int sh[256];
    int t = threadIdx.x;
    int v0 = (t < NB_SCAN) ? g_bsum[t] : 0;
    sh[t] = v0;
    __syncthreads();
    for (int off = 1; off < 256; off <<= 1) {
        int v = sh[t];
        int add = (t >= off) ? sh[t - off] : 0;
        __syncthreads();
        sh[t] = v + add;
        __syncthreads();
    }
    if (t < NB_SCAN) g_boff[t] = (t == 0) ? 0 : sh[t - 1];
    if (t == NB_SCAN - 1) g_rp[V_NODES] = sh[t];
}

__global__ void scan3_k() {
    __shared__ int sh[256];
    int t = threadIdx.x;
    int i = blockIdx.x * 256 + t;
    int c = (i < V_NODES) ? g_cnt[i] : 0;
    sh[t] = c;
    __syncthreads();
    for (int off = 1; off < 256; off <<= 1) {
        int v = sh[t];
        int add = (t >= off) ? sh[t - off] : 0;
        __syncthreads();
        sh[t] = v + add;
        __syncthreads();
    }
    if (i < V_NODES) g_rp[i] = g_boff[blockIdx.x] + sh[t] - c;
}

__global__ void scatter_k(const int* __restrict__ rows, const int* __restrict__ cols,
                          const float* __restrict__ vals, int E) {
    int e = blockIdx.x * blockDim.x + threadIdx.x;
    int stride = gridDim.x * blockDim.x;
    for (; e < E; e += stride) {
        int r = rows[e];
        int p = g_rp[r] + atomicAdd(&g_cnt[r], 1);
        g_ccol[p] = cols[e];
        g_cval[p] = vals[e];
    }
}

// ---------------- SpMM (pure): y[v, c*128:(c+1)*128] = sum_e val * x[col, same slice] ----
// One warp per (row, chunk). Lanes cooperatively prefetch 32 edges (coalesced),
// then shuffle-broadcast -> 32 independent gathers in flight (MLP ~32).
// Chunk-major block ordering keeps the active 25.6MB source slice L2-resident.
__global__ void spmm_k(int yi, int xi) {
    int w = (blockIdx.x * blockDim.x + threadIdx.x) >> 5;
    if (w >= V_NODES) return;
    int lane = threadIdx.x & 31;
    int chunk = blockIdx.y;

    const float4* __restrict__ x4 = (const float4*)pick(xi);
    float4* __restrict__ y4 = (float4*)pick(yi);
    int cbase = chunk * 32;   // float4 offset within 128-float4 row

    float4 acc = make_float4(0.f, 0.f, 0.f, 0.f);

    int p0 = g_rp[w], p1 = g_rp[w + 1];
    for (int pb = p0; pb < p1; pb += 32) {
        int pc = pb + lane;
        int   c   = 0;
        float val = 0.f;
        if (pc < p1) { c = g_ccol[pc]; val = g_cval[pc]; }
        int n = p1 - pb; if (n > 32) n = 32;
#pragma unroll 4
        for (int j = 0; j < n; j++) {
            int   cj = __shfl_sync(0xffffffffu, c, j);
            float vj = __shfl_sync(0xffffffffu, val, j);
            float4 xv = x4[(size_t)cj * 128 + cbase + lane];
            acc.x += vj * xv.x;
            acc.y += vj * xv.y;
            acc.z += vj * xv.z;
            acc.w += vj * xv.w;
        }
    }

    y4[(size_t)w * 128 + cbase + lane] = acc;
}

// ---------------- fused 3xTF32 GEMM: g_acc = [P0..P4](200000,640) @ g_wc(640,128) ------
#define A_STRIDE 36
#define B_STRIDE 136
#define GEMM_SMEM ((2 * 128 * A_STRIDE + 2 * 32 * B_STRIDE) * 4)   // 71680 B

__global__ __launch_bounds__(256, 2) void gemm3_k() {
    extern __shared__ float sh[];
    float* Ah = sh;                          // 128 x 36
    float* Al = Ah + 128 * A_STRIDE;
    float* Bh = Al + 128 * A_STRIDE;         // 32 x 136
    float* Bl = Bh + 32 * B_STRIDE;

    int tid = threadIdx.x;
    int warp = tid >> 5, lane = tid & 31;
    int g = lane >> 2, tig = lane & 3;
    int wm = warp >> 1, wn = warp & 1;       // 4 x 2 warp grid
    int m_warp = wm * 32, n_warp = wn * 64;
    size_t row0 = (size_t)blockIdx.x * 128;

    float acc[2][8][4];
#pragma unroll
    for (int mt = 0; mt < 2; mt++)
#pragma unroll
        for (int nt = 0; nt < 8; nt++)
#pragma unroll
            for (int j = 0; j < 4; j++) acc[mt][nt][j] = 0.f;

    for (int kb = 0; kb < 20; kb++) {
        int kk  = kb >> 2;             // power buffer
        int ks0 = (kb & 3) * 32;       // column offset within 128
        const float* A = pick(kk);
        const float* W = g_wc + kk * (CIN * COUT);

        __syncthreads();   // previous iteration's reads done

        // A tile: 128 rows x 32 cols -> hi/lo smem
#pragma unroll
        for (int q = 0; q < 4; q++) {
            int i = tid + 256 * q;       // 0..1023 float4s
            int r = i >> 3, cg = i & 7;
            size_t ar = row0 + r;
            if (ar >= MROWS) ar = MROWS - 1;
            float4 v = *(const float4*)(A + ar * 128 + ks0 + cg * 4);
            float* dh = Ah + r * A_STRIDE + cg * 4;
            float* dl = Al + r * A_STRIDE + cg * 4;
            float vv[4] = {v.x, v.y, v.z, v.w};
#pragma unroll
            for (int j = 0; j < 4; j++) {
                uint32_t hb = f2tf32(vv[j]);
                float hf = __uint_as_float(hb);
                dh[j] = hf;
                dl[j] = __uint_as_float(f2tf32(vv[j] - hf));
            }
        }

        // B tile: 32 rows x 128 cols -> hi/lo smem
#pragma unroll
        for (int q = 0; q < 4; q++) {
            int i = tid + 256 * q;
            int r = i >> 5, cg = i & 31;
            float4 v = *(const float4*)(W + (ks0 + r) * 128 + cg * 4);
            float* dh = Bh + r * B_STRIDE + cg * 4;
            float* dl = Bl + r * B_STRIDE + cg * 4;
            float vv[4] = {v.x, v.y, v.z, v.w};
#pragma unroll
            for (int j = 0; j < 4; j++) {
                uint32_t hb = f2tf32(vv[j]);
                float hf = __uint_as_float(hb);
                dh[j] = hf;
                dl[j] = __uint_as_float(f2tf32(vv[j] - hf));
            }
        }
        __syncthreads();

#pragma unroll
        for (int ks = 0; ks < 4; ks++) {
            int k0 = ks * 8;
            uint32_t ah[2][4], al[2][4];
#pragma unroll
            for (int mt = 0; mt < 2; mt++) {
                int rb = m_warp + mt * 16;
                ah[mt][0] = __float_as_uint(Ah[(rb + g) * A_STRIDE + k0 + tig]);
                ah[mt][1] = __float_as_uint(Ah[(rb + g + 8) * A_STRIDE + k0 + tig]);
                ah[mt][2] = __float_as_uint(Ah[(rb + g) * A_STRIDE + k0 + tig + 4]);
                ah[mt][3] = __float_as_uint(Ah[(rb + g + 8) * A_STRIDE + k0 + tig + 4]);
                al[mt][0] = __float_as_uint(Al[(rb + g) * A_STRIDE + k0 + tig]);
                al[mt][1] = __float_as_uint(Al[(rb + g + 8) * A_STRIDE + k0 + tig]);
                al[mt][2] = __float_as_uint(Al[(rb + g) * A_STRIDE + k0 + tig + 4]);
                al[mt][3] = __float_as_uint(Al[(rb + g + 8) * A_STRIDE + k0 + tig + 4]);
            }
#pragma unroll
            for (int nt = 0; nt < 8; nt++) {
                int nb = n_warp + nt * 8;
                uint32_t bh[2], bl[2];
                bh[0] = __float_as_uint(Bh[(k0 + tig) * B_STRIDE + nb + g]);
                bh[1] = __float_as_uint(Bh[(k0 + tig + 4) * B_STRIDE + nb + g]);
                bl[0] = __float_as_uint(Bl[(k0 + tig) * B_STRIDE + nb + g]);
                bl[1] = __float_as_uint(Bl[(k0 + tig + 4) * B_STRIDE + nb + g]);
#pragma unroll
                for (int mt = 0; mt < 2; mt++) {
                    mma_tf32(acc[mt][nt], al[mt], bh);   // lo*hi
                    mma_tf32(acc[mt][nt], ah[mt], bl);   // hi*lo
                    mma_tf32(acc[mt][nt], ah[mt], bh);   // hi*hi
                }
            }
        }
    }

    // epilogue -> g_acc (fp32)
#pragma unroll
    for (int mt = 0; mt < 2; mt++) {
#pragma unroll
        for (int nt = 0; nt < 8; nt++) {
            size_t r0 = row0 + m_warp + mt * 16 + g;
            size_t r1 = r0 + 8;
            int c = n_warp + nt * 8 + 2 * tig;
            if (r0 < MROWS)
                *(float2*)(g_acc + r0 * 128 + c) = make_float2(acc[mt][nt][0], acc[mt][nt][1]);
            if (r1 < MROWS)
                *(float2*)(g_acc + r1 * 128 + c) = make_float2(acc[mt][nt][2], acc[mt][nt][3]);
        }
    }
}

// ---------------- launch ----------------
extern "C" void kernel_launch(void* const* d_in, const int* in_sizes, int n_in,
                              void* d_out, int out_size) {
    const float* x        = (const float*)d_in[0];
    const float* lap_vals = (const float*)d_in[1];
    const float* weight   = (const float*)d_in[2];
    const float* bias     = (const float*)d_in[3];
    const int*   rows     = (const int*)d_in[4];
    const int*   cols     = (const int*)d_in[5];
    int E = in_sizes[1];
    float* out = (float*)d_out;

    cudaFuncSetAttribute(gemm3_k, cudaFuncAttributeMaxDynamicSharedMemorySize, GEMM_SMEM);

    dim3 tb(32, 32);
    dim3 tg((V_NODES + 31) / 32, FEAT / 32);

    // layout in: P0
    transpose_in<<<tg, tb>>>(x);

    // combined weights (independent of recurrence)
    wcomb_k<<<(CIN * COUT + 255) / 256, 256>>>(weight);

    // CSR build
    zero_cnt<<<(V_NODES + 255) / 256, 256>>>();
    count_k<<<1024, 256>>>(rows, E);
    scan1_k<<<NB_SCAN, 256>>>();
    scan2_k<<<1, 256>>>();
    scan3_k<<<NB_SCAN, 256>>>();
    zero_cnt<<<(V_NODES + 255) / 256, 256>>>();
    scatter_k<<<1024, 256>>>(rows, cols, lap_vals, E);

    // pure powers P1..P4
    dim3 spgrid((V_NODES * 32 + 255) / 256, NCHUNK);
    spmm_k<<<spgrid, 256>>>(1, 0);   // P1 = L P0
    spmm_k<<<spgrid, 256>>>(2, 1);   // P2 = L P1
    spmm_k<<<spgrid, 256>>>(3, 2);   // P3 = L P2
    spmm_k<<<spgrid, 256>>>(4, 3);   // P4 = L P3

    // fused projection: g_acc = [P0..P4] @ [W~0..W~4]
    gemm3_k<<<(MROWS + 127) / 128, 256, GEMM_SMEM>>>();

    // layout out + bias
    write_out<<<tg, tb>>>(out, bias);
}

// round 7
// speedup vs baseline: 1.3975x; 1.0207x over previous
#include <cuda_runtime.h>
#include <cstdint>

#define V_NODES 50000
#define FEAT    512          // B * Cin
#define CIN     128
#define COUT    128
#define BATCH   4
#define MROWS   (V_NODES * BATCH)   // 200000
#define MAXE    800000
#define KORD    5
#define NB_SCAN ((V_NODES + 255) / 256)   // 196
#define NCHUNK  4                          // 4 x 128-feature slices

// ---------------- static device scratch (no allocations allowed) ----------------
__device__ float g_b0[(size_t)V_NODES * FEAT];
__device__ float g_b1[(size_t)V_NODES * FEAT];
__device__ float g_b2[(size_t)V_NODES * FEAT];
__device__ float g_b3[(size_t)V_NODES * FEAT];
__device__ float g_b4[(size_t)V_NODES * FEAT];
__device__ float g_wc[KORD * CIN * COUT];   // combined weights
__device__ int   g_rp[V_NODES + 1];
__device__ int   g_cnt[V_NODES];
__device__ int   g_bsum[NB_SCAN];
__device__ int   g_boff[NB_SCAN];
__device__ int   g_ccol[MAXE];
__device__ float g_cval[MAXE];

__device__ __forceinline__ float* pick(int i) {
    switch (i) {
        case 0: return g_b0;
        case 1: return g_b1;
        case 2: return g_b2;
        case 3: return g_b3;
        default: return g_b4;
    }
}

// ---------------- tf32 helpers ----------------
__device__ __forceinline__ uint32_t f2tf32(float f) {
    uint32_t r;
    asm("cvt.rna.tf32.f32 %0, %1;" : "=r"(r) : "f"(f));
    return r;
}

__device__ __forceinline__ void split_tf32(float f, uint32_t& hi, uint32_t& lo) {
    uint32_t h = f2tf32(f);
    hi = h;
    lo = f2tf32(f - __uint_as_float(h));
}

__device__ __forceinline__ void mma_tf32(float* d, const uint32_t* a, const uint32_t* b) {
    asm volatile(
        "mma.sync.aligned.m16n8k8.row.col.f32.tf32.tf32.f32 "
        "{%0,%1,%2,%3}, {%4,%5,%6,%7}, {%8,%9}, {%0,%1,%2,%3};"
        : "+f"(d[0]), "+f"(d[1]), "+f"(d[2]), "+f"(d[3])
        : "r"(a[0]), "r"(a[1]), "r"(a[2]), "r"(a[3]), "r"(b[0]), "r"(b[1]));
}

// ---------------- cp.async helpers ----------------
__device__ __forceinline__ void cp_async16(void* smem_dst, const void* gmem_src) {
    uint32_t s = (uint32_t)__cvta_generic_to_shared(smem_dst);
    asm volatile("cp.async.cg.shared.global [%0], [%1], 16;" :: "r"(s), "l"(gmem_src));
}
__device__ __forceinline__ void cp_commit() {
    asm volatile("cp.async.commit_group;");
}
template <int N>
__device__ __forceinline__ void cp_wait() {
    asm volatile("cp.async.wait_group %0;" :: "n"(N));
}

// ---------------- transpose: x (512, V) -> g_b0 (V, 512) ----------------
__global__ void transpose_in(const float* __restrict__ x) {
    __shared__ float tile[32][33];
    int v = blockIdx.x * 32 + threadIdx.x;
    int f = blockIdx.y * 32 + threadIdx.y;
    if (v < V_NODES)
        tile[threadIdx.y][threadIdx.x] = x[(size_t)f * V_NODES + v];
    __syncthreads();
    int vo = blockIdx.x * 32 + threadIdx.y;
    int fo = blockIdx.y * 32 + threadIdx.x;
    if (vo < V_NODES)
        g_b0[(size_t)vo * FEAT + fo] = tile[threadIdx.x][threadIdx.y];
}

// ---------------- combined weights ----------------
// T0..T4 = {P0, P1, 2P2-P0, 4P3-3P1, 8P4-8P2+P0};  out = sum_k Tk Wk = sum_j Pj W~j
__global__ void wcomb_k(const float* __restrict__ w) {
    int i = blockIdx.x * 256 + threadIdx.x;
    if (i >= CIN * COUT) return;
    const int S = CIN * COUT;
    float w0 = w[i], w1 = w[i + S], w2 = w[i + 2 * S], w3 = w[i + 3 * S], w4 = w[i + 4 * S];
    g_wc[i]         = w0 - w2 + w4;
    g_wc[i + S]     = w1 - 3.f * w3;
    g_wc[i + 2 * S] = 2.f * w2 - 8.f * w4;
    g_wc[i + 3 * S] = 4.f * w3;
    g_wc[i + 4 * S] = 8.f * w4;
}

// ---------------- CSR build ----------------
__global__ void zero_cnt() {
    int i = blockIdx.x * blockDim.x + threadIdx.x;
    if (i < V_NODES) g_cnt[i] = 0;
}

__global__ void count_k(const int* __restrict__ rows, int E) {
    int e = blockIdx.x * blockDim.x + threadIdx.x;
    int stride = gridDim.x * blockDim.x;
    for (; e < E; e += stride) atomicAdd(&g_cnt[rows[e]], 1);
}

__global__ void scan1_k() {
    __shared__ int sh[256];
    int t = threadIdx.x;
    int i = blockIdx.x * 256 + t;
    int c = (i < V_NODES) ? g_cnt[i] : 0;
    sh[t] = c;
    __syncthreads();
    for (int off = 1; off < 256; off <<= 1) {
        int v = sh[t];
        int add = (t >= off) ? sh[t - off] : 0;
        __syncthreads();
        sh[t] = v + add;
        __syncthreads();
    }
    if (t == 255) g_bsum[blockIdx.x] = sh[255];
}

__global__ void scan2_k() {
    __shared__ int sh[256];
    int t = threadIdx.x;
    int v0 = (t < NB_SCAN) ? g_bsum[t] : 0;
    sh[t] = v0;
    __syncthreads();
    for (int off = 1; off < 256; off <<= 1) {
        int v = sh[t];
        int add = (t >= off) ? sh[t - off] : 0;
        __syncthreads();
        sh[t] = v + add;
        __syncthreads();
    }
    if (t < NB_SCAN) g_boff[t] = (t == 0) ? 0 : sh[t - 1];
    if (t == NB_SCAN - 1) g_rp[V_NODES] = sh[t];
}

// expand + zero g_cnt in-place (scatter needs cnt=0 next)
__global__ void scan3_k() {
    __shared__ int sh[256];
    int t = threadIdx.x;
    int i = blockIdx.x * 256 + t;
    int c = (i < V_NODES) ? g_cnt[i] : 0;
    sh[t] = c;
    __syncthreads();
    for (int off = 1; off < 256; off <<= 1) {
        int v = sh[t];
        int add = (t >= off) ? sh[t - off] : 0;
        __syncthreads();
        sh[t] = v + add;
        __syncthreads();
    }
    if (i < V_NODES) {
        g_rp[i] = g_boff[blockIdx.x] + sh[t] - c;
        g_cnt[i] = 0;
    }
}

__global__ void scatter_k(const int* __restrict__ rows, const int* __restrict__ cols,
                          const float* __restrict__ vals, int E) {
    int e = blockIdx.x * blockDim.x + threadIdx.x;
    int stride = gridDim.x * blockDim.x;
    for (; e < E; e += stride) {
        int r = rows[e];
        int p = g_rp[r] + atomicAdd(&g_cnt[r], 1);
        g_ccol[p] = cols[e];
        g_cval[p] = vals[e];
    }
}

// ---------------- SpMM (pure): y[v, c*128:(c+1)*128] = sum_e val * x[col, slice] ----
__global__ void spmm_k(int yi, int xi) {
    int w = (blockIdx.x * blockDim.x + threadIdx.x) >> 5;
    if (w >= V_NODES) return;
    int lane = threadIdx.x & 31;
    int chunk = blockIdx.y;

    const float4* __restrict__ x4 = (const float4*)pick(xi);
    float4* __restrict__ y4 = (float4*)pick(yi);
    int cbase = chunk * 32;   // float4 offset within 128-float4 row

    float4 acc = make_float4(0.f, 0.f, 0.f, 0.f);

    int p0 = g_rp[w], p1 = g_rp[w + 1];
    for (int pb = p0; pb < p1; pb += 32) {
        int pc = pb + lane;
        int   c   = 0;
        float val = 0.f;
        if (pc < p1) { c = g_ccol[pc]; val = g_cval[pc]; }
        int n = p1 - pb; if (n > 32) n = 32;
#pragma unroll 4
        for (int j = 0; j < n; j++) {
            int   cj = __shfl_sync(0xffffffffu, c, j);
            float vj = __shfl_sync(0xffffffffu, val, j);
            float4 xv = x4[(size_t)cj * 128 + cbase + lane];
            acc.x += vj * xv.x;
            acc.y += vj * xv.y;
            acc.z += vj * xv.z;
            acc.w += vj * xv.w;
        }
    }

    y4[(size_t)w * 128 + cbase + lane] = acc;
}

// ---------------- fused 3xTF32 GEMM + epilogue: out = ([P0..P4] @ g_wc)^T + bias ----
// Raw fp32 smem, double-buffered via cp.async; tf32 hi/lo split done in registers
// at fragment load. Epilogue transposes through smem and writes out directly.
#define A_STRIDE 36     // 32 k + 4 pad  (frag banks 4g+tig: conflict-free)
#define B_STRIDE 132    // 128 n + 4 pad (frag banks 4tig+g: conflict-free)
#define A_STAGE  (128 * A_STRIDE)          // 4608 floats
#define B_STAGE  (32 * B_STRIDE)           // 4224 floats
#define GEMM_SMEM ((2 * (A_STAGE + B_STAGE)) * 4)   // 70656 B
#define EPI_STRIDE 132

__global__ __launch_bounds__(256, 2) void gemm3_k(float* __restrict__ out,
                                                  const float* __restrict__ bias) {
    extern __shared__ float sh[];
    float* As[2] = { sh, sh + A_STAGE };
    float* Bs[2] = { sh + 2 * A_STAGE, sh + 2 * A_STAGE + B_STAGE };

    int tid = threadIdx.x;
    int warp = tid >> 5, lane = tid & 31;
    int g = lane >> 2, tig = lane & 3;
    int wm = warp >> 1, wn = warp & 1;       // 4 x 2 warp grid
    int m_warp = wm * 32, n_warp = wn * 64;
    size_t row0 = (size_t)blockIdx.x * 128;

    float acc[2][8][4];
#pragma unroll
    for (int mt = 0; mt < 2; mt++)
#pragma unroll
        for (int nt = 0; nt < 8; nt++)
#pragma unroll
            for (int j = 0; j < 4; j++) acc[mt][nt][j] = 0.f;

    // ---- stage loader (cp.async, raw fp32) ----
    auto load_stage = [&](int s, int kb) {
        int kk  = kb >> 2;
        int ks0 = (kb & 3) * 32;
        const float* A = pick(kk);
        const float* W = g_wc + kk * (CIN * COUT);
#pragma unroll
        for (int q = 0; q < 4; q++) {
            int i = tid + 256 * q;          // A: 1024 float4s
            int r = i >> 3, cg = i & 7;
            size_t ar = row0 + r;
            if (ar >= MROWS) ar = MROWS - 1;
            cp_async16(As[s] + r * A_STRIDE + cg * 4, A + ar * 128 + ks0 + cg * 4);
        }
#pragma unroll
        for (int q = 0; q < 4; q++) {
            int i = tid + 256 * q;          // B: 1024 float4s
            int r = i >> 5, cg = i & 31;
            cp_async16(Bs[s] + r * B_STRIDE + cg * 4, W + (ks0 + r) * 128 + cg * 4);
        }
        cp_commit();
    };

    load_stage(0, 0);

    for (int kb = 0; kb < 20; kb++) {
        int s = kb & 1;
        if (kb < 19) load_stage(s ^ 1, kb + 1);
        if (kb < 19) cp_wait<1>(); else cp_wait<0>();
        __syncthreads();

        const float* Ar = As[s];
        const float* Br = Bs[s];
#pragma unroll
        for (int ks = 0; ks < 4; ks++) {
            int k0 = ks * 8;
            uint32_t ah[2][4], al[2][4];
#pragma unroll
            for (int mt = 0; mt < 2; mt++) {
                int rb = m_warp + mt * 16;
                split_tf32(Ar[(rb + g)     * A_STRIDE + k0 + tig],     ah[mt][0], al[mt][0]);
                split_tf32(Ar[(rb + g + 8) * A_STRIDE + k0 + tig],     ah[mt][1], al[mt][1]);
                split_tf32(Ar[(rb + g)     * A_STRIDE + k0 + tig + 4], ah[mt][2], al[mt][2]);
                split_tf32(Ar[(rb + g + 8) * A_STRIDE + k0 + tig + 4], ah[mt][3], al[mt][3]);
            }
#pragma unroll
            for (int nt = 0; nt < 8; nt++) {
                int nb = n_warp + nt * 8;
                uint32_t bh[2], bl[2];
                split_tf32(Br[(k0 + tig)     * B_STRIDE + nb + g], bh[0], bl[0]);
                split_tf32(Br[(k0 + tig + 4) * B_STRIDE + nb + g], bh[1], bl[1]);
#pragma unroll
                for (int mt = 0; mt < 2; mt++) {
                    mma_tf32(acc[mt][nt], al[mt], bh);   // lo*hi
                    mma_tf32(acc[mt][nt], ah[mt], bl);   // hi*lo
                    mma_tf32(acc[mt][nt], ah[mt], bh);   // hi*hi
                }
            }
        }
        __syncthreads();   // stage s consumed; safe to refill next iteration
    }

    // ---- epilogue: transpose via smem, add bias, write out ----
    // smem layout: epi[o][m'] with m' = v_local + 32*b  (v_local = m_local>>2, b = m_local&3)
    float* epi = sh;   // 128 x EPI_STRIDE floats = 67584 B <= GEMM_SMEM
    __syncthreads();

#pragma unroll
    for (int mt = 0; mt < 2; mt++) {
#pragma unroll
        for (int nt = 0; nt < 8; nt++) {
#pragma unroll
            for (int j = 0; j < 4; j++) {
                int c = n_warp + nt * 8 + 2 * tig + (j & 1);
                int m_loc = m_warp + mt * 16 + g + 8 * (j >> 1);
                int mp = (m_loc >> 2) + 32 * (m_loc & 3);
                epi[c * EPI_STRIDE + mp] = acc[mt][nt][j];
            }
        }
    }
    __syncthreads();

    int v0 = (int)(row0 >> 2);   // block's first node
    for (int p = warp; p < 512; p += 8) {
        int b = p >> 7, o = p & 127;
        float bv = bias[o];
        int vg = v0 + lane;
        float val = epi[o * EPI_STRIDE + 32 * b + lane] + bv;
        if (vg < V_NODES)
            out[(size_t)(b * 128 + o) * V_NODES + vg] = val;
    }
}

// ---------------- launch ----------------
extern "C" void kernel_launch(void* const* d_in, const int* in_sizes, int n_in,
                              void* d_out, int out_size) {
    const float* x        = (const float*)d_in[0];
    const float* lap_vals = (const float*)d_in[1];
    const float* weight   = (const float*)d_in[2];
    const float* bias     = (const float*)d_in[3];
    const int*   rows     = (const int*)d_in[4];
    const int*   cols     = (const int*)d_in[5];
    int E = in_sizes[1];
    float* out = (float*)d_out;

    cudaFuncSetAttribute(gemm3_k, cudaFuncAttributeMaxDynamicSharedMemorySize, GEMM_SMEM);

    dim3 tb(32, 32);
    dim3 tg((V_NODES + 31) / 32, FEAT / 32);

    // layout in: P0
    transpose_in<<<tg, tb>>>(x);

    // combined weights
    wcomb_k<<<(CIN * COUT + 255) / 256, 256>>>(weight);

    // CSR build
    zero_cnt<<<(V_NODES + 255) / 256, 256>>>();
    count_k<<<1024, 256>>>(rows, E);
    scan1_k<<<NB_SCAN, 256>>>();
    scan2_k<<<1, 256>>>();
    scan3_k<<<NB_SCAN, 256>>>();      // also zeroes g_cnt for scatter
    scatter_k<<<1024, 256>>>(rows, cols, lap_vals, E);

    // pure powers P1..P4
    dim3 spgrid((V_NODES * 32 + 255) / 256, NCHUNK);
    spmm_k<<<spgrid, 256>>>(1, 0);   // P1 = L P0
    spmm_k<<<spgrid, 256>>>(2, 1);   // P2 = L P1
    spmm_k<<<spgrid, 256>>>(3, 2);   // P3 = L P2
    spmm_k<<<spgrid, 256>>>(4, 3);   // P4 = L P3

    // fused projection + transpose + bias: out = ([P0..P4] @ W~)^T + bias
    gemm3_k<<<(MROWS + 127) / 128, 256, GEMM_SMEM>>>(out, bias);
}

// round 8
// speedup vs baseline: 1.6414x; 1.1745x over previous
#include <cuda_runtime.h>
#include <cuda_fp16.h>
#include <cstdint>

#define V_NODES 50000
#define FEAT    512          // B * Cin
#define CIN     128
#define COUT    128
#define BATCH   4
#define MROWS   (V_NODES * BATCH)   // 200000
#define MAXE    800000
#define KORD    5
#define NB_SCAN ((V_NODES + 255) / 256)   // 196
#define NCHUNK  4                          // 4 x 128-feature slices

// ---------------- static device scratch (no allocations allowed) ----------------
__device__ float  g_b0[(size_t)V_NODES * FEAT];     // P0 fp32 (GEMM k=0 operand)
__device__ __half g_h0[(size_t)V_NODES * FEAT];     // P0 fp16 (SpMM gather source)
__device__ __half g_h1[(size_t)V_NODES * FEAT];
__device__ __half g_h2[(size_t)V_NODES * FEAT];
__device__ __half g_h3[(size_t)V_NODES * FEAT];
__device__ __half g_h4[(size_t)V_NODES * FEAT];
__device__ float  g_wc[KORD * CIN * COUT];          // combined weights
__device__ int    g_rp[V_NODES + 1];
__device__ int    g_cnt[V_NODES];
__device__ int    g_bsum[NB_SCAN];
__device__ int    g_boff[NB_SCAN];
__device__ int    g_ccol[MAXE];
__device__ float  g_cval[MAXE];

__device__ __forceinline__ __half* pick_h(int i) {
    switch (i) {
        case 0: return g_h0;
        case 1: return g_h1;
        case 2: return g_h2;
        case 3: return g_h3;
        default: return g_h4;
    }
}

// ---------------- tf32 helpers ----------------
__device__ __forceinline__ uint32_t f2tf32(float f) {
    uint32_t r;
    asm("cvt.rna.tf32.f32 %0, %1;" : "=r"(r) : "f"(f));
    return r;
}

__device__ __forceinline__ void split_tf32(float f, uint32_t& hi, uint32_t& lo) {
    uint32_t h = f2tf32(f);
    hi = h;
    lo = f2tf32(f - __uint_as_float(h));
}

__device__ __forceinline__ void mma_tf32(float* d, const uint32_t* a, const uint32_t* b) {
    asm volatile(
        "mma.sync.aligned.m16n8k8.row.col.f32.tf32.tf32.f32 "
        "{%0,%1,%2,%3}, {%4,%5,%6,%7}, {%8,%9}, {%0,%1,%2,%3};"
        : "+f"(d[0]), "+f"(d[1]), "+f"(d[2]), "+f"(d[3])
        : "r"(a[0]), "r"(a[1]), "r"(a[2]), "r"(a[3]), "r"(b[0]), "r"(b[1]));
}

// ---------------- cp.async helpers ----------------
__device__ __forceinline__ void cp_async16(void* smem_dst, const void* gmem_src) {
    uint32_t s = (uint32_t)__cvta_generic_to_shared(smem_dst);
    asm volatile("cp.async.cg.shared.global [%0], [%1], 16;" :: "r"(s), "l"(gmem_src));
}
__device__ __forceinline__ void cp_commit() {
    asm volatile("cp.async.commit_group;");
}
template <int N>
__device__ __forceinline__ void cp_wait() {
    asm volatile("cp.async.wait_group %0;" :: "n"(N));
}

// ---------------- transpose: x (512, V) -> g_b0 fp32 + g_h0 fp16 ----------------
__global__ void transpose_in(const float* __restrict__ x) {
    __shared__ float tile[32][33];
    int v = blockIdx.x * 32 + threadIdx.x;
    int f = blockIdx.y * 32 + threadIdx.y;
    if (v < V_NODES)
        tile[threadIdx.y][threadIdx.x] = x[(size_t)f * V_NODES + v];
    __syncthreads();
    int vo = blockIdx.x * 32 + threadIdx.y;
    int fo = blockIdx.y * 32 + threadIdx.x;
    if (vo < V_NODES) {
        float val = tile[threadIdx.x][threadIdx.y];
        g_b0[(size_t)vo * FEAT + fo] = val;
        g_h0[(size_t)vo * FEAT + fo] = __float2half(val);
    }
}

// ---------------- combined weights ----------------
// T0..T4 = {P0, P1, 2P2-P0, 4P3-3P1, 8P4-8P2+P0};  out = sum_k Tk Wk = sum_j Pj W~j
__global__ void wcomb_k(const float* __restrict__ w) {
    int i = blockIdx.x * 256 + threadIdx.x;
    if (i >= CIN * COUT) return;
    const int S = CIN * COUT;
    float w0 = w[i], w1 = w[i + S], w2 = w[i + 2 * S], w3 = w[i + 3 * S], w4 = w[i + 4 * S];
    g_wc[i]         = w0 - w2 + w4;
    g_wc[i + S]     = w1 - 3.f * w3;
    g_wc[i + 2 * S] = 2.f * w2 - 8.f * w4;
    g_wc[i + 3 * S] = 4.f * w3;
    g_wc[i + 4 * S] = 8.f * w4;
}

// ---------------- CSR build ----------------
__global__ void zero_cnt() {
    int i = blockIdx.x * blockDim.x + threadIdx.x;
    if (i < V_NODES) g_cnt[i] = 0;
}

__global__ void count_k(const int* __restrict__ rows, int E) {
    int e = blockIdx.x * blockDim.x + threadIdx.x;
    int stride = gridDim.x * blockDim.x;
    for (; e < E; e += stride) atomicAdd(&g_cnt[rows[e]], 1);
}

__global__ void scan1_k() {
    __shared__ int sh[256];
    int t = threadIdx.x;
    int i = blockIdx.x * 256 + t;
    int c = (i < V_NODES) ? g_cnt[i] : 0;
    sh[t] = c;
    __syncthreads();
    for (int off = 1; off < 256; off <<= 1) {
        int v = sh[t];
        int add = (t >= off) ? sh[t - off] : 0;
        __syncthreads();
        sh[t] = v + add;
        __syncthreads();
    }
    if (t == 255) g_bsum[blockIdx.x] = sh[255];
}

__global__ void scan2_k() {
    __shared__ int sh[256];
    int t = threadIdx.x;
    int v0 = (t < NB_SCAN) ? g_bsum[t] : 0;
    sh[t] = v0;
    __syncthreads();
    for (int off = 1; off < 256; off <<= 1) {
        int v = sh[t];
        int add = (t >= off) ? sh[t - off] : 0;
        __syncthreads();
        sh[t] = v + add;
        __syncthreads();
    }
    if (t < NB_SCAN) g_boff[t] = (t == 0) ? 0 : sh[t - 1];
    if (t == NB_SCAN - 1) g_rp[V_NODES] = sh[t];
}

// expand + zero g_cnt in-place (scatter needs cnt=0 next)
__global__ void scan3_k() {
    __shared__ int sh[256];
    int t = threadIdx.x;
    int i = blockIdx.x * 256 + t;
    int c = (i < V_NODES) ? g_cnt[i] : 0;
    sh[t] = c;
    __syncthreads();
    for (int off = 1; off < 256; off <<= 1) {
        int v = sh[t];
        int add = (t >= off) ? sh[t - off] : 0;
        __syncthreads();
        sh[t] = v + add;
        __syncthreads();
    }
    if (i < V_NODES) {
        g_rp[i] = g_boff[blockIdx.x] + sh[t] - c;
        g_cnt[i] = 0;
    }
}

__global__ void scatter_k(const int* __restrict__ rows, const int* __restrict__ cols,
                          const float* __restrict__ vals, int E) {
    int e = blockIdx.x * blockDim.x + threadIdx.x;
    int stride = gridDim.x * blockDim.x;
    for (; e < E; e += stride) {
        int r = rows[e];
        int p = g_rp[r] + atomicAdd(&g_cnt[r], 1);
        g_ccol[p] = cols[e];
        g_cval[p] = vals[e];
    }
}

// ---------------- SpMM (fp16 in/out, fp32 accumulate) ----------------
// y[v, chunk*128 : +128] = sum_e val * x[col, slice].  One warp per (row, chunk):
// lane covers 4 features (one uint2 = 4 halfs = 8B); 32-edge coalesced prefetch +
// shuffle broadcast -> 32 independent 256B gathers in flight.
__global__ void spmm_k(int yi, int xi) {
    int w = (blockIdx.x * blockDim.x + threadIdx.x) >> 5;
    if (w >= V_NODES) return;
    int lane = threadIdx.x & 31;
    int chunk = blockIdx.y;

    const uint2* __restrict__ x2 = (const uint2*)pick_h(xi);
    uint2* __restrict__ y2 = (uint2*)pick_h(yi);
    int cbase = chunk * 32 + lane;   // uint2 offset within 128-uint2 row

    float4 acc = make_float4(0.f, 0.f, 0.f, 0.f);

    int p0 = g_rp[w], p1 = g_rp[w + 1];
    for (int pb = p0; pb < p1; pb += 32) {
        int pc = pb + lane;
        int   c   = 0;
        float val = 0.f;
        if (pc < p1) { c = g_ccol[pc]; val = g_cval[pc]; }
        int n = p1 - pb; if (n > 32) n = 32;
#pragma unroll 4
        for (int j = 0; j < n; j++) {
            int   cj = __shfl_sync(0xffffffffu, c, j);
            float vj = __shfl_sync(0xffffffffu, val, j);
            uint2 raw = x2[(size_t)cj * 128 + cbase];
            float2 f01 = __half22float2(*(const __half2*)&raw.x);
            float2 f23 = __half22float2(*(const __half2*)&raw.y);
            acc.x += vj * f01.x;
            acc.y += vj * f01.y;
            acc.z += vj * f23.x;
            acc.w += vj * f23.y;
        }
    }

    uint2 outv;
    *(__half2*)&outv.x = __floats2half2_rn(acc.x, acc.y);
    *(__half2*)&outv.y = __floats2half2_rn(acc.z, acc.w);
    y2[(size_t)w * 128 + cbase] = outv;
}

// ---------------- fused GEMM + epilogue: out = ([P0..P4] @ g_wc)^T + bias ----
// kb 0..3  : A = g_b0 fp32 tile, 3xTF32 (hi/lo split in registers).
// kb 4..19 : A = g_h[kk] fp16 tile -> tf32 exact (lo = 0), 2 MMAs.
// B (weights) fp32, hi/lo split in registers. cp.async double-buffered.
#define A_STRIDE   36    // fp32 A: 32 k + 4 pad
#define A16_STRIDE 40    // fp16 A: 32 k + 8 pad (80B rows: 16B-aligned, odd word stride)
#define B_STRIDE   132   // 128 n + 4 pad
#define A_STAGE_F  (128 * A_STRIDE)        // 4608 floats = 18432 B (>= 128*40 halfs = 10240 B)
#define B_STAGE    (32 * B_STRIDE)         // 4224 floats
#define GEMM_SMEM  ((2 * (A_STAGE_F + B_STAGE)) * 4)   // 70656 B
#define EPI_STRIDE 132

__global__ __launch_bounds__(256, 2) void gemm3_k(float* __restrict__ out,
                                                  const float* __restrict__ bias) {
    extern __shared__ float sh[];
    float* As[2] = { sh, sh + A_STAGE_F };
    float* Bs[2] = { sh + 2 * A_STAGE_F, sh + 2 * A_STAGE_F + B_STAGE };

    int tid = threadIdx.x;
    int warp = tid >> 5, lane = tid & 31;
    int g = lane >> 2, tig = lane & 3;
    int wm = warp >> 1, wn = warp & 1;       // 4 x 2 warp grid
    int m_warp = wm * 32, n_warp = wn * 64;
    size_t row0 = (size_t)blockIdx.x * 128;

    float acc[2][8][4];
#pragma unroll
    for (int mt = 0; mt < 2; mt++)
#pragma unroll
        for (int nt = 0; nt < 8; nt++)
#pragma unroll
            for (int j = 0; j < 4; j++) acc[mt][nt][j] = 0.f;

    // ---- stage loader (cp.async) ----
    auto load_stage = [&](int s, int kb) {
        int kk  = kb >> 2;
        int ks0 = (kb & 3) * 32;
        const float* W = g_wc + kk * (CIN * COUT);
        if (kb < 4) {
            // fp32 A from g_b0: 1024 x 16B
#pragma unroll
            for (int q = 0; q < 4; q++) {
                int i = tid + 256 * q;
                int r = i >> 3, cg = i & 7;
                size_t ar = row0 + r;
                if (ar >= MROWS) ar = MROWS - 1;
                cp_async16(As[s] + r * A_STRIDE + cg * 4, g_b0 + ar * 128 + ks0 + cg * 4);
            }
        } else {
            // fp16 A from g_h[kk]: 512 x 16B (row = 32 halfs = 4 chunks)
            const __half* Ah = pick_h(kk);
            __half* dst = (__half*)As[s];
#pragma unroll
            for (int q = 0; q < 2; q++) {
                int i = tid + 256 * q;
                int r = i >> 2, cg = i & 3;
                size_t ar = row0 + r;
                if (ar >= MROWS) ar = MROWS - 1;
                cp_async16(dst + r * A16_STRIDE + cg * 8, Ah + ar * 128 + ks0 + cg * 8);
            }
        }
#pragma unroll
        for (int q = 0; q < 4; q++) {
            int i = tid + 256 * q;          // B: 1024 x 16B
            int r = i >> 5, cg = i & 31;
            cp_async16(Bs[s] + r * B_STRIDE + cg * 4, W + (ks0 + r) * 128 + cg * 4);
        }
        cp_commit();
    };

    load_stage(0, 0);

    for (int kb = 0; kb < 20; kb++) {
        int s = kb & 1;
        if (kb < 19) load_stage(s ^ 1, kb + 1);
        if (kb < 19) cp_wait<1>(); else cp_wait<0>();
        __syncthreads();

        const float* Br = Bs[s];
        if (kb < 4) {
            const float* Ar = As[s];
#pragma unroll
            for (int ks = 0; ks < 4; ks++) {
                int k0 = ks * 8;
                uint32_t ah[2][4], al[2][4];
#pragma unroll
                for (int mt = 0; mt < 2; mt++) {
                    int rb = m_warp + mt * 16;
                    split_tf32(Ar[(rb + g)     * A_STRIDE + k0 + tig],     ah[mt][0], al[mt][0]);
                    split_tf32(Ar[(rb + g + 8) * A_STRIDE + k0 + tig],     ah[mt][1], al[mt][1]);
                    split_tf32(Ar[(rb + g)     * A_STRIDE + k0 + tig + 4], ah[mt][2], al[mt][2]);
                    split_tf32(Ar[(rb + g + 8) * A_STRIDE + k0 + tig + 4], ah[mt][3], al[mt][3]);
                }
#pragma unroll
                for (int nt = 0; nt < 8; nt++) {
                    int nb = n_warp + nt * 8;
                    uint32_t bh[2], bl[2];
                    split_tf32(Br[(k0 + tig)     * B_STRIDE + nb + g], bh[0], bl[0]);
                    split_tf32(Br[(k0 + tig + 4) * B_STRIDE + nb + g], bh[1], bl[1]);
#pragma unroll
                    for (int mt = 0; mt < 2; mt++) {
                        mma_tf32(acc[mt][nt], al[mt], bh);   // lo*hi
                        mma_tf32(acc[mt][nt], ah[mt], bl);   // hi*lo
                        mma_tf32(acc[mt][nt], ah[mt], bh);   // hi*hi
                    }
                }
            }
        } else {
            const __half* Ar = (const __half*)As[s];
#pragma unroll
            for (int ks = 0; ks < 4; ks++) {
                int k0 = ks * 8;
                uint32_t ah[2][4];
#pragma unroll
                for (int mt = 0; mt < 2; mt++) {
                    int rb = m_warp + mt * 16;
                    ah[mt][0] = f2tf32(__half2float(Ar[(rb + g)     * A16_STRIDE + k0 + tig]));
                    ah[mt][1] = f2tf32(__half2float(Ar[(rb + g + 8) * A16_STRIDE + k0 + tig]));
                    ah[mt][2] = f2tf32(__half2float(Ar[(rb + g)     * A16_STRIDE + k0 + tig + 4]));
                    ah[mt][3] = f2tf32(__half2float(Ar[(rb + g + 8) * A16_STRIDE + k0 + tig + 4]));
                }
#pragma unroll
                for (int nt = 0; nt < 8; nt++) {
                    int nb = n_warp + nt * 8;
                    uint32_t bh[2], bl[2];
                    split_tf32(Br[(k0 + tig)     * B_STRIDE + nb + g], bh[0], bl[0]);
                    split_tf32(Br[(k0 + tig + 4) * B_STRIDE + nb + g], bh[1], bl[1]);
#pragma unroll
                    for (int mt = 0; mt < 2; mt++) {
                        mma_tf32(acc[mt][nt], ah[mt], bl);   // a (exact) * b_lo
                        mma_tf32(acc[mt][nt], ah[mt], bh);   // a (exact) * b_hi
                    }
                }
            }
        }
        __syncthreads();   // stage s consumed; safe to refill next iteration
    }

    // ---- epilogue: transpose via smem, add bias, write out ----
    // epi[o][m'] with m' = v_local + 32*b  (v_local = m_local>>2, b = m_local&3)
    float* epi = sh;   // 128 x EPI_STRIDE floats = 67584 B <= GEMM_SMEM
    __syncthreads();

#pragma unroll
    for (int mt = 0; mt < 2; mt++) {
#pragma unroll
        for (int nt = 0; nt < 8; nt++) {
#pragma unroll
            for (int j = 0; j < 4; j++) {
                int c = n_warp + nt * 8 + 2 * tig + (j & 1);
                int m_loc = m_warp + mt * 16 + g + 8 * (j >> 1);
                int mp = (m_loc >> 2) + 32 * (m_loc & 3);
                epi[c * EPI_STRIDE + mp] = acc[mt][nt][j];
            }
        }
    }
    __syncthreads();

    int v0 = (int)(row0 >> 2);   // block's first node
    for (int p = warp; p < 512; p += 8) {
        int b = p >> 7, o = p & 127;
        float bv = bias[o];
        int vg = v0 + lane;
        float val = epi[o * EPI_STRIDE + 32 * b + lane] + bv;
        if (vg < V_NODES)
            out[(size_t)(b * 128 + o) * V_NODES + vg] = val;
    }
}

// ---------------- launch ----------------
extern "C" void kernel_launch(void* const* d_in, const int* in_sizes, int n_in,
                              void* d_out, int out_size) {
    const float* x        = (const float*)d_in[0];
    const float* lap_vals = (const float*)d_in[1];
    const float* weight   = (const float*)d_in[2];
    const float* bias     = (const float*)d_in[3];
    const int*   rows     = (const int*)d_in[4];
    const int*   cols     = (const int*)d_in[5];
    int E = in_sizes[1];
    float* out = (float*)d_out;

    cudaFuncSetAttribute(gemm3_k, cudaFuncAttributeMaxDynamicSharedMemorySize, GEMM_SMEM);

    dim3 tb(32, 32);
    dim3 tg((V_NODES + 31) / 32, FEAT / 32);

    // layout in: P0 (fp32 + fp16 copy)
    transpose_in<<<tg, tb>>>(x);

    // combined weights
    wcomb_k<<<(CIN * COUT + 255) / 256, 256>>>(weight);

    // CSR build
    zero_cnt<<<(V_NODES + 255) / 256, 256>>>();
    count_k<<<1024, 256>>>(rows, E);
    scan1_k<<<NB_SCAN, 256>>>();
    scan2_k<<<1, 256>>>();
    scan3_k<<<NB_SCAN, 256>>>();      // also zeroes g_cnt for scatter
    scatter_k<<<1024, 256>>>(rows, cols, lap_vals, E);

    // pure powers P1..P4 (fp16 storage, fp32 accumulate)
    dim3 spgrid((V_NODES * 32 + 255) / 256, NCHUNK);
    spmm_k<<<spgrid, 256>>>(1, 0);   // P1 = L P0
    spmm_k<<<spgrid, 256>>>(2, 1);   // P2 = L P1
    spmm_k<<<spgrid, 256>>>(3, 2);   // P3 = L P2
    spmm_k<<<spgrid, 256>>>(4, 3);   // P4 = L P3

    // fused projection + transpose + bias
    gemm3_k<<<(MROWS + 127) / 128, 256, GEMM_SMEM>>>(out, bias);
}

// round 10
// speedup vs baseline: 2.2133x; 1.3484x over previous
#include <cuda_runtime.h>
#include <cuda_fp16.h>
#include <cstdint>

#define V_NODES 50000
#define FEAT    512          // B * Cin
#define CIN     128
#define COUT    128
#define BATCH   4
#define MROWS   (V_NODES * BATCH)   // 200000
#define MAXE    800000
#define KORD    5
#define NB_SCAN ((V_NODES + 255) / 256)   // 196
#define NCHUNK  4                          // 4 x 128-feature slices

// ---------------- static device scratch (no allocations allowed) ----------------
__device__ __half g_h0[(size_t)V_NODES * FEAT];     // P0..P4 fp16
__device__ __half g_h1[(size_t)V_NODES * FEAT];
__device__ __half g_h2[(size_t)V_NODES * FEAT];
__device__ __half g_h3[(size_t)V_NODES * FEAT];
__device__ __half g_h4[(size_t)V_NODES * FEAT];
__device__ __half g_wh[KORD * CIN * COUT];          // combined weights hi (layout [k][o][i])
__device__ __half g_wl[KORD * CIN * COUT];          // combined weights lo (layout [k][o][i])
__device__ int    g_rp[V_NODES + 1];
__device__ int    g_cnt[V_NODES];
__device__ int    g_bsum[NB_SCAN];
__device__ int    g_boff[NB_SCAN];
__device__ int    g_ccol[MAXE];
__device__ float  g_cval[MAXE];

__device__ __forceinline__ __half* pick_h(int i) {
    switch (i) {
        case 0: return g_h0;
        case 1: return g_h1;
        case 2: return g_h2;
        case 3: return g_h3;
        default: return g_h4;
    }
}

// ---------------- fp16 mma ----------------
__device__ __forceinline__ void mma_f16(float* d, const uint32_t* a, const uint32_t* b) {
    asm volatile(
        "mma.sync.aligned.m16n8k16.row.col.f32.f16.f16.f32 "
        "{%0,%1,%2,%3}, {%4,%5,%6,%7}, {%8,%9}, {%0,%1,%2,%3};"
        : "+f"(d[0]), "+f"(d[1]), "+f"(d[2]), "+f"(d[3])
        : "r"(a[0]), "r"(a[1]), "r"(a[2]), "r"(a[3]), "r"(b[0]), "r"(b[1]));
}

// ---------------- cp.async helpers ----------------
__device__ __forceinline__ void cp_async16(void* smem_dst, const void* gmem_src) {
    uint32_t s = (uint32_t)__cvta_generic_to_shared(smem_dst);
    asm volatile("cp.async.cg.shared.global [%0], [%1], 16;" :: "r"(s), "l"(gmem_src));
}
__device__ __forceinline__ void cp_commit() {
    asm volatile("cp.async.commit_group;");
}
template <int N>
__device__ __forceinline__ void cp_wait() {
    asm volatile("cp.async.wait_group %0;" :: "n"(N));
}

// ---------------- transpose: x (512, V) -> g_h0 (V, 512) fp16 ----------------
__global__ void transpose_in(const float* __restrict__ x) {
    __shared__ float tile[32][33];
    int v = blockIdx.x * 32 + threadIdx.x;
    int f = blockIdx.y * 32 + threadIdx.y;
    if (v < V_NODES)
        tile[threadIdx.y][threadIdx.x] = x[(size_t)f * V_NODES + v];
    __syncthreads();
    int vo = blockIdx.x * 32 + threadIdx.y;
    int fo = blockIdx.y * 32 + threadIdx.x;
    if (vo < V_NODES)
        g_h0[(size_t)vo * FEAT + fo] = __float2half(tile[threadIdx.x][threadIdx.y]);
}

// ---------------- combined weights -> fp16 hi/lo, transposed [k][o][i] ----------------
// T0..T4 = {P0, P1, 2P2-P0, 4P3-3P1, 8P4-8P2+P0};  out = sum_k Tk Wk = sum_j Pj W~j
__global__ void wcomb_k(const float* __restrict__ w) {
    int i = blockIdx.x * 256 + threadIdx.x;   // i = iin*128 + o
    if (i >= CIN * COUT) return;
    const int S = CIN * COUT;
    float w0 = w[i], w1 = w[i + S], w2 = w[i + 2 * S], w3 = w[i + 3 * S], w4 = w[i + 4 * S];
    float wt[KORD];
    wt[0] = w0 - w2 + w4;
    wt[1] = w1 - 3.f * w3;
    wt[2] = 2.f * w2 - 8.f * w4;
    wt[3] = 4.f * w3;
    wt[4] = 8.f * w4;
    int iin = i >> 7, o = i & 127;
#pragma unroll
    for (int j = 0; j < KORD; j++) {
        __half h = __float2half(wt[j]);
        g_wh[j * S + o * 128 + iin] = h;
        g_wl[j * S + o * 128 + iin] = __float2half(wt[j] - __half2float(h));
    }
}

// ---------------- CSR build ----------------
__global__ void zero_cnt() {
    int i = blockIdx.x * blockDim.x + threadIdx.x;
    if (i < V_NODES) g_cnt[i] = 0;
}

__global__ void count_k(const int* __restrict__ rows, int E) {
    int e = blockIdx.x * blockDim.x + threadIdx.x;
    int stride = gridDim.x * blockDim.x;
    for (; e < E; e += stride) atomicAdd(&g_cnt[rows[e]], 1);
}

__global__ void scan1_k() {
    __shared__ int sh[256];
    int t = threadIdx.x;
    int i = blockIdx.x * 256 + t;
    int c = (i < V_NODES) ? g_cnt[i] : 0;
    sh[t] = c;
    __syncthreads();
    for (int off = 1; off < 256; off <<= 1) {
        int v = sh[t];
        int add = (t >= off) ? sh[t - off] : 0;
        __syncthreads();
        sh[t] = v + add;
        __syncthreads();
    }
    if (t == 255) g_bsum[blockIdx.x] = sh[255];
}

__global__ void scan2_k() {
    __shared__ int sh[256];
    int t = threadIdx.x;
    int v0 = (t < NB_SCAN) ? g_bsum[t] : 0;
    sh[t] = v0;
    __syncthreads();
    for (int off = 1; off < 256; off <<= 1) {
        int v = sh[t];
        int add = (t >= off) ? sh[t - off] : 0;
        __syncthreads();
        sh[t] = v + add;
        __syncthreads();
    }
    if (t < NB_SCAN) g_boff[t] = (t == 0) ? 0 : sh[t - 1];
    if (t == NB_SCAN - 1) g_rp[V_NODES] = sh[t];
}

// expand + zero g_cnt in-place (scatter needs cnt=0 next)
__global__ void scan3_k() {
    __shared__ int sh[256];
    int t = threadIdx.x;
    int i = blockIdx.x * 256 + t;
    int c = (i < V_NODES) ? g_cnt[i] : 0;
    sh[t] = c;
    __syncthreads();
    for (int off = 1; off < 256; off <<= 1) {
        int v = sh[t];
        int add = (t >= off) ? sh[t - off] : 0;
        __syncthreads();
        sh[t] = v + add;
        __syncthreads();
    }
    if (i < V_NODES) {
        g_rp[i] = g_boff[blockIdx.x] + sh[t] - c;
        g_cnt[i] = 0;
    }
}

__global__ void scatter_k(const int* __restrict__ rows, const int* __restrict__ cols,
                          const float* __restrict__ vals, int E) {
    int e = blockIdx.x * blockDim.x + threadIdx.x;
    int stride = gridDim.x * blockDim.x;
    for (; e < E; e += stride) {
        int r = rows[e];
        int p = g_rp[r] + atomicAdd(&g_cnt[r], 1);
        g_ccol[p] = cols[e];
        g_cval[p] = vals[e];
    }
}

// ---------------- SpMM (fp16 in/out, fp32 accumulate) ----------------
__global__ void spmm_k(int yi, int xi) {
    int w = (blockIdx.x * blockDim.x + threadIdx.x) >> 5;
    if (w >= V_NODES) return;
    int lane = threadIdx.x & 31;
    int chunk = blockIdx.y;

    const uint2* __restrict__ x2 = (const uint2*)pick_h(xi);
    uint2* __restrict__ y2 = (uint2*)pick_h(yi);
    int cbase = chunk * 32 + lane;   // uint2 offset within 128-uint2 row

    float4 acc = make_float4(0.f, 0.f, 0.f, 0.f);

    int p0 = g_rp[w], p1 = g_rp[w + 1];
    for (int pb = p0; pb < p1; pb += 32) {
        int pc = pb + lane;
        int   c   = 0;
        float val = 0.f;
        if (pc < p1) { c = g_ccol[pc]; val = g_cval[pc]; }
        int n = p1 - pb; if (n > 32) n = 32;
#pragma unroll 4
        for (int j = 0; j < n; j++) {
            int   cj = __shfl_sync(0xffffffffu, c, j);
            float vj = __shfl_sync(0xffffffffu, val, j);
            uint2 raw = x2[(size_t)cj * 128 + cbase];
            float2 f01 = __half22float2(*(const __half2*)&raw.x);
            float2 f23 = __half22float2(*(const __half2*)&raw.y);
            acc.x += vj * f01.x;
            acc.y += vj * f01.y;
            acc.z += vj * f23.x;
            acc.w += vj * f23.y;
        }
    }

    uint2 outv;
    *(__half2*)&outv.x = __floats2half2_rn(acc.x, acc.y);
    *(__half2*)&outv.y = __floats2half2_rn(acc.z, acc.w);
    y2[(size_t)w * 128 + cbase] = outv;
}

// ---------------- fused fp16-MMA GEMM + epilogue: out = ([P0..P4] @ W~)^T + bias ----
// A fp16 (exact), W~ precomputed fp16 hi/lo -> acc = A*Wl + A*Wh per k16-chunk.
// Smem stride 40 halfs (20 words): 20g+tig mod 32 covers all banks -> conflict-free.
// B smem is [n][k] (k-contiguous) matching the col-major B fragment pairing.
#define HS       40                         // half stride
#define A_ST     (128 * HS)                 // 5120 halfs = 10240 B
#define B_ST     (128 * HS)                 // per hi/lo tile
#define STAGE_H  (A_ST + 2 * B_ST)          // 15360 halfs = 30720 B
#define GEMM_SMEM 67584                     // max(2*30720, epi 128*132*4)
#define EPI_STRIDE 132

__global__ __launch_bounds__(256, 2) void gemm3_k(float* __restrict__ out,
                                                  const float* __restrict__ bias) {
    extern __shared__ __align__(16) __half shh[];
    int tid = threadIdx.x;
    int warp = tid >> 5, lane = tid & 31;
    int g = lane >> 2, tig = lane & 3;
    int wm = warp >> 1, wn = warp & 1;       // 4 x 2 warp grid
    int m_warp = wm * 32, n_warp = wn * 64;
    size_t row0 = (size_t)blockIdx.x * 128;

    float acc[2][8][4];
#pragma unroll
    for (int mt = 0; mt < 2; mt++)
#pragma unroll
        for (int nt = 0; nt < 8; nt++)
#pragma unroll
            for (int j = 0; j < 4; j++) acc[mt][nt][j] = 0.f;

    // ---- stage loader (cp.async): A 512 + Bh 512 + Bl 512 chunks of 16B ----
    auto load_stage = [&](int s, int kb) {
        int kk  = kb >> 2;
        int ks0 = (kb & 3) * 32;
        const __half* A  = pick_h(kk);
        const __half* Wh = g_wh + kk * (CIN * COUT);
        const __half* Wl = g_wl + kk * (CIN * COUT);
        __half* As = shh + s * STAGE_H;
        __half* Bh = As + A_ST;
        __half* Bl = Bh + B_ST;
#pragma unroll
        for (int q = 0; q < 2; q++) {
            int i = tid + 256 * q;           // A: 512 x 16B (row = 4 chunks of 8 halfs)
            int r = i >> 2, cg = i & 3;
            size_t ar = row0 + r;
            if (ar >= MROWS) ar = MROWS - 1;
            cp_async16(As + r * HS + cg * 8, A + ar * 128 + ks0 + cg * 8);
        }
#pragma unroll
        for (int q = 0; q < 2; q++) {
            int i = tid + 256 * q;           // Bh: 512 x 16B
            int r = i >> 2, cg = i & 3;
            cp_async16(Bh + r * HS + cg * 8, Wh + r * 128 + ks0 + cg * 8);
        }
#pragma unroll
        for (int q = 0; q < 2; q++) {
            int i = tid + 256 * q;           // Bl: 512 x 16B
            int r = i >> 2, cg = i & 3;
            cp_async16(Bl + r * HS + cg * 8, Wl + r * 128 + ks0 + cg * 8);
        }
        cp_commit();
    };

    load_stage(0, 0);

    for (int kb = 0; kb < 20; kb++) {
        int s = kb & 1;
        if (kb < 19) load_stage(s ^ 1, kb + 1);
        if (kb < 19) cp_wait<1>(); else cp_wait<0>();
        __syncthreads();

        const __half* Ar  = shh + s * STAGE_H;
        const __half* Bhr = Ar + A_ST;
        const __half* Blr = Bhr + B_ST;

#pragma unroll
        for (int kc = 0; kc < 2; kc++) {
            int k0 = kc * 16;
            uint32_t a[2][4];
#pragma unroll
            for (int mt = 0; mt < 2; mt++) {
                int rb = m_warp + mt * 16;
                a[mt][0] = *(const uint32_t*)(Ar + (rb + g)     * HS + k0 + 2 * tig);
                a[mt][1] = *(const uint32_t*)(Ar + (rb + g + 8) * HS + k0 + 2 * tig);
                a[mt][2] = *(const uint32_t*)(Ar + (rb + g)     * HS + k0 + 2 * tig + 8);
                a[mt][3] = *(const uint32_t*)(Ar + (rb + g + 8) * HS + k0 + 2 * tig + 8);
            }
#pragma unroll
            for (int nt = 0; nt < 8; nt++) {
                int nb = n_warp + nt * 8;
                uint32_t bh[2], bl[2];
                bh[0] = *(const uint32_t*)(Bhr + (nb + g) * HS + k0 + 2 * tig);
                bh[1] = *(const uint32_t*)(Bhr + (nb + g) * HS + k0 + 2 * tig + 8);
                bl[0] = *(const uint32_t*)(Blr + (nb + g) * HS + k0 + 2 * tig);
                bl[1] = *(const uint32_t*)(Blr + (nb + g) * HS + k0 + 2 * tig + 8);
#pragma unroll
                for (int mt = 0; mt < 2; mt++) {
                    mma_f16(acc[mt][nt], a[mt], bl);   // A * W_lo
                    mma_f16(acc[mt][nt], a[mt], bh);   // A * W_hi
                }
            }
        }
        __syncthreads();   // stage s consumed; safe to refill next iteration
    }

    // ---- epilogue: transpose via smem, add bias, write out ----
    // epi[o][m'] with m' = v_local + 32*b  (v_local = m_local>>2, b = m_local&3)
    float* epi = (float*)shh;   // 128 x EPI_STRIDE floats = 67584 B
    __syncthreads();

#pragma unroll
    for (int mt = 0; mt < 2; mt++) {
#pragma unroll
        for (int nt = 0; nt < 8; nt++) {
#pragma unroll
            for (int j = 0; j < 4; j++) {
                int c = n_warp + nt * 8 + 2 * tig + (j & 1);
                int m_loc = m_warp + mt * 16 + g + 8 * (j >> 1);
                int mp = (m_loc >> 2) + 32 * (m_loc & 3);
                epi[c * EPI_STRIDE + mp] = acc[mt][nt][j];
            }
        }
    }
    __syncthreads();

    int v0 = (int)(row0 >> 2);   // block's first node
    for (int p = warp; p < 512; p += 8) {
        int b = p >> 7, o = p & 127;
        float bv = bias[o];
        int vg = v0 + lane;
        float val = epi[o * EPI_STRIDE + 32 * b + lane] + bv;
        if (vg < V_NODES)
            out[(size_t)(b * 128 + o) * V_NODES + vg] = val;
    }
}

// ---------------- launch ----------------
extern "C" void kernel_launch(void* const* d_in, const int* in_sizes, int n_in,
                              void* d_out, int out_size) {
    const float* x        = (const float*)d_in[0];
    const float* lap_vals = (const float*)d_in[1];
    const float* weight   = (const float*)d_in[2];
    const float* bias     = (const float*)d_in[3];
    const int*   rows     = (const int*)d_in[4];
    const int*   cols     = (const int*)d_in[5];
    int E = in_sizes[1];
    float* out = (float*)d_out;

    cudaFuncSetAttribute(gemm3_k, cudaFuncAttributeMaxDynamicSharedMemorySize, GEMM_SMEM);

    dim3 tb(32, 32);
    dim3 tg((V_NODES + 31) / 32, FEAT / 32);

    // layout in: P0 fp16
    transpose_in<<<tg, tb>>>(x);

    // combined weights (fp16 hi/lo, transposed)
    wcomb_k<<<(CIN * COUT + 255) / 256, 256>>>(weight);

    // CSR build
    zero_cnt<<<(V_NODES + 255) / 256, 256>>>();
    count_k<<<1024, 256>>>(rows, E);
    scan1_k<<<NB_SCAN, 256>>>();
    scan2_k<<<1, 256>>>();
    scan3_k<<<NB_SCAN, 256>>>();      // also zeroes g_cnt for scatter
    scatter_k<<<1024, 256>>>(rows, cols, lap_vals, E);

    // pure powers P1..P4 (fp16 storage, fp32 accumulate)
    dim3 spgrid((V_NODES * 32 + 255) / 256, NCHUNK);
    spmm_k<<<spgrid, 256>>>(1, 0);   // P1 = L P0
    spmm_k<<<spgrid, 256>>>(2, 1);   // P2 = L P1
    spmm_k<<<spgrid, 256>>>(3, 2);   // P3 = L P2
    spmm_k<<<spgrid, 256>>>(4, 3);   // P4 = L P3

    // fused projection + transpose + bias
    gemm3_k<<<(MROWS + 127) / 128, 256, GEMM_SMEM>>>(out, bias);
}

// round 11
// speedup vs baseline: 2.5835x; 1.1673x over previous
#include <cuda_runtime.h>
#include <cuda_fp16.h>
#include <cstdint>

#define V_NODES 50000
#define FEAT    512          // B * Cin
#define CIN     128
#define COUT    128
#define BATCH   4
#define MROWS   (V_NODES * BATCH)   // 200000
#define MAXE    800000
#define KORD    5
#define NB_SCAN ((V_NODES + 255) / 256)   // 196
#define NCHUNK  2                          // 2 x 256-feature slices

// ---------------- static device scratch (no allocations allowed) ----------------
__device__ __half g_h0[(size_t)V_NODES * FEAT];     // P0..P4 fp16
__device__ __half g_h1[(size_t)V_NODES * FEAT];
__device__ __half g_h2[(size_t)V_NODES * FEAT];
__device__ __half g_h3[(size_t)V_NODES * FEAT];
__device__ __half g_h4[(size_t)V_NODES * FEAT];
__device__ __half g_wh[KORD * CIN * COUT];          // combined weights hi (layout [k][o][i])
__device__ __half g_wl[KORD * CIN * COUT];          // combined weights lo (layout [k][o][i])
__device__ int    g_rp[V_NODES + 1];
__device__ int    g_cnt[V_NODES];
__device__ int    g_bsum[NB_SCAN];
__device__ int    g_boff[NB_SCAN];
__device__ int    g_ccol[MAXE];
__device__ float  g_cval[MAXE];

__device__ __forceinline__ __half* pick_h(int i) {
    switch (i) {
        case 0: return g_h0;
        case 1: return g_h1;
        case 2: return g_h2;
        case 3: return g_h3;
        default: return g_h4;
    }
}

// ---------------- fp16 mma ----------------
__device__ __forceinline__ void mma_f16(float* d, const uint32_t* a, const uint32_t* b) {
    asm volatile(
        "mma.sync.aligned.m16n8k16.row.col.f32.f16.f16.f32 "
        "{%0,%1,%2,%3}, {%4,%5,%6,%7}, {%8,%9}, {%0,%1,%2,%3};"
        : "+f"(d[0]), "+f"(d[1]), "+f"(d[2]), "+f"(d[3])
        : "r"(a[0]), "r"(a[1]), "r"(a[2]), "r"(a[3]), "r"(b[0]), "r"(b[1]));
}

// ---------------- cp.async helpers ----------------
__device__ __forceinline__ void cp_async16(void* smem_dst, const void* gmem_src) {
    uint32_t s = (uint32_t)__cvta_generic_to_shared(smem_dst);
    asm volatile("cp.async.cg.shared.global [%0], [%1], 16;" :: "r"(s), "l"(gmem_src));
}
__device__ __forceinline__ void cp_commit() {
    asm volatile("cp.async.commit_group;");
}
template <int N>
__device__ __forceinline__ void cp_wait() {
    asm volatile("cp.async.wait_group %0;" :: "n"(N));
}

// ---------------- transpose: x (512, V) -> g_h0 (V, 512) fp16; also zeroes g_cnt ----
__global__ void transpose_in(const float* __restrict__ x) {
    __shared__ float tile[32][33];
    // fold zero_cnt into the y==0 slab (1563 blocks x 1024 threads >= V_NODES)
    if (blockIdx.y == 0) {
        int t = threadIdx.y * 32 + threadIdx.x;
        int i = blockIdx.x * 1024 + t;
        if (i < V_NODES) g_cnt[i] = 0;
    }
    int v = blockIdx.x * 32 + threadIdx.x;
    int f = blockIdx.y * 32 + threadIdx.y;
    if (v < V_NODES)
        tile[threadIdx.y][threadIdx.x] = x[(size_t)f * V_NODES + v];
    __syncthreads();
    int vo = blockIdx.x * 32 + threadIdx.y;
    int fo = blockIdx.y * 32 + threadIdx.x;
    if (vo < V_NODES)
        g_h0[(size_t)vo * FEAT + fo] = __float2half(tile[threadIdx.x][threadIdx.y]);
}

// ---------------- combined weights -> fp16 hi/lo, transposed [k][o][i] ----------------
// T0..T4 = {P0, P1, 2P2-P0, 4P3-3P1, 8P4-8P2+P0};  out = sum_k Tk Wk = sum_j Pj W~j
__global__ void wcomb_k(const float* __restrict__ w) {
    int i = blockIdx.x * 256 + threadIdx.x;   // i = iin*128 + o
    if (i >= CIN * COUT) return;
    const int S = CIN * COUT;
    float w0 = w[i], w1 = w[i + S], w2 = w[i + 2 * S], w3 = w[i + 3 * S], w4 = w[i + 4 * S];
    float wt[KORD];
    wt[0] = w0 - w2 + w4;
    wt[1] = w1 - 3.f * w3;
    wt[2] = 2.f * w2 - 8.f * w4;
    wt[3] = 4.f * w3;
    wt[4] = 8.f * w4;
    int iin = i >> 7, o = i & 127;
#pragma unroll
    for (int j = 0; j < KORD; j++) {
        __half h = __float2half(wt[j]);
        g_wh[j * S + o * 128 + iin] = h;
        g_wl[j * S + o * 128 + iin] = __float2half(wt[j] - __half2float(h));
    }
}

// ---------------- CSR build ----------------
__global__ void count_k(const int* __restrict__ rows, int E) {
    int e = blockIdx.x * blockDim.x + threadIdx.x;
    int stride = gridDim.x * blockDim.x;
    for (; e < E; e += stride) atomicAdd(&g_cnt[rows[e]], 1);
}

__global__ void scan1_k() {
    __shared__ int sh[256];
    int t = threadIdx.x;
    int i = blockIdx.x * 256 + t;
    int c = (i < V_NODES) ? g_cnt[i] : 0;
    sh[t] = c;
    __syncthreads();
    for (int off = 1; off < 256; off <<= 1) {
        int v = sh[t];
        int add = (t >= off) ? sh[t - off] : 0;
        __syncthreads();
        sh[t] = v + add;
        __syncthreads();
    }
    if (t == 255) g_bsum[blockIdx.x] = sh[255];
}

__global__ void scan2_k() {
    __shared__ int sh[256];
    int t = threadIdx.x;
    int v0 = (t < NB_SCAN) ? g_bsum[t] : 0;
    sh[t] = v0;
    __syncthreads();
    for (int off = 1; off < 256; off <<= 1) {
        int v = sh[t];
        int add = (t >= off) ? sh[t - off] : 0;
        __syncthreads();
        sh[t] = v + add;
        __syncthreads();
    }
    if (t < NB_SCAN) g_boff[t] = (t == 0) ? 0 : sh[t - 1];
    if (t == NB_SCAN - 1) g_rp[V_NODES] = sh[t];
}

// expand + zero g_cnt in-place (scatter needs cnt=0 next)
__global__ void scan3_k() {
    __shared__ int sh[256];
    int t = threadIdx.x;
    int i = blockIdx.x * 256 + t;
    int c = (i < V_NODES) ? g_cnt[i] : 0;
    sh[t] = c;
    __syncthreads();
    for (int off = 1; off < 256; off <<= 1) {
        int v = sh[t];
        int add = (t >= off) ? sh[t - off] : 0;
        __syncthreads();
        sh[t] = v + add;
        __syncthreads();
    }
    if (i < V_NODES) {
        g_rp[i] = g_boff[blockIdx.x] + sh[t] - c;
        g_cnt[i] = 0;
    }
}

__global__ void scatter_k(const int* __restrict__ rows, const int* __restrict__ cols,
                          const float* __restrict__ vals, int E) {
    int e = blockIdx.x * blockDim.x + threadIdx.x;
    int stride = gridDim.x * blockDim.x;
    for (; e < E; e += stride) {
        int r = rows[e];
        int p = g_rp[r] + atomicAdd(&g_cnt[r], 1);
        g_ccol[p] = cols[e];
        g_cval[p] = vals[e];
    }
}

// ---------------- SpMM (fp16 in/out, fp32 accumulate) ----------------
// y[v, chunk*256 : +256] = sum_e val * x[col, slice].  One warp per (row, chunk):
// lane covers 8 features (one uint4 = 8 halfs = 16B); 32-edge coalesced prefetch +
// shuffle broadcast -> independent 512B gathers in flight.
__global__ void spmm_k(int yi, int xi) {
    int w = (blockIdx.x * blockDim.x + threadIdx.x) >> 5;
    if (w >= V_NODES) return;
    int lane = threadIdx.x & 31;

    const uint4* __restrict__ x4 = (const uint4*)pick_h(xi);
    uint4* __restrict__ y4 = (uint4*)pick_h(yi);
    int cbase = blockIdx.y * 32 + lane;   // uint4 offset within 64-uint4 row

    float acc[8];
#pragma unroll
    for (int q = 0; q < 8; q++) acc[q] = 0.f;

    int p0 = g_rp[w], p1 = g_rp[w + 1];
    for (int pb = p0; pb < p1; pb += 32) {
        int pc = pb + lane;
        int   c   = 0;
        float val = 0.f;
        if (pc < p1) { c = g_ccol[pc]; val = g_cval[pc]; }
        int n = p1 - pb; if (n > 32) n = 32;
#pragma unroll 4
        for (int j = 0; j < n; j++) {
            int   cj = __shfl_sync(0xffffffffu, c, j);
            float vj = __shfl_sync(0xffffffffu, val, j);
            uint4 raw = x4[(size_t)cj * 64 + cbase];
            const __half2* h2 = (const __half2*)&raw;
#pragma unroll
            for (int q = 0; q < 4; q++) {
                float2 f = __half22float2(h2[q]);
                acc[2 * q]     += vj * f.x;
                acc[2 * q + 1] += vj * f.y;
            }
        }
    }

    uint4 outv;
    __half2* oh = (__half2*)&outv;
#pragma unroll
    for (int q = 0; q < 4; q++) oh[q] = __floats2half2_rn(acc[2 * q], acc[2 * q + 1]);
    y4[(size_t)w * 64 + cbase] = outv;
}

// ---------------- fused fp16-MMA GEMM + epilogue: out = ([P0..P4] @ W~)^T + bias ----
// A fp16 (exact). W~ hi/lo compensation only for the k=0 term (kb<4) — for k>=1 the
// A operand already carries fp16 quantization, so W_lo adds nothing measurable.
#define HS       40                         // half stride (20 words: conflict-free)
#define A_ST     (128 * HS)                 // 5120 halfs = 10240 B
#define B_ST     (128 * HS)                 // per hi/lo tile
#define STAGE_H  (A_ST + 2 * B_ST)          // 15360 halfs = 30720 B
#define GEMM_SMEM 67584                     // max(2*30720, epi 128*132*4)
#define EPI_STRIDE 132

__global__ __launch_bounds__(256, 2) void gemm3_k(float* __restrict__ out,
                                                  const float* __restrict__ bias) {
    extern __shared__ __align__(16) __half shh[];
    int tid = threadIdx.x;
    int warp = tid >> 5, lane = tid & 31;
    int g = lane >> 2, tig = lane & 3;
    int wm = warp >> 1, wn = warp & 1;       // 4 x 2 warp grid
    int m_warp = wm * 32, n_warp = wn * 64;
    size_t row0 = (size_t)blockIdx.x * 128;

    float acc[2][8][4];
#pragma unroll
    for (int mt = 0; mt < 2; mt++)
#pragma unroll
        for (int nt = 0; nt < 8; nt++)
#pragma unroll
            for (int j = 0; j < 4; j++) acc[mt][nt][j] = 0.f;

    // ---- stage loader (cp.async): A 512 + Bh 512 (+ Bl 512 for kb<4) chunks of 16B ----
    auto load_stage = [&](int s, int kb) {
        int kk  = kb >> 2;
        int ks0 = (kb & 3) * 32;
        const __half* A  = pick_h(kk);
        const __half* Wh = g_wh + kk * (CIN * COUT);
        __half* As = shh + s * STAGE_H;
        __half* Bh = As + A_ST;
        __half* Bl = Bh + B_ST;
#pragma unroll
        for (int q = 0; q < 2; q++) {
            int i = tid + 256 * q;           // A: 512 x 16B (row = 4 chunks of 8 halfs)
            int r = i >> 2, cg = i & 3;
            size_t ar = row0 + r;
            if (ar >= MROWS) ar = MROWS - 1;
            cp_async16(As + r * HS + cg * 8, A + ar * 128 + ks0 + cg * 8);
        }
#pragma unroll
        for (int q = 0; q < 2; q++) {
            int i = tid + 256 * q;           // Bh: 512 x 16B
            int r = i >> 2, cg = i & 3;
            cp_async16(Bh + r * HS + cg * 8, Wh + r * 128 + ks0 + cg * 8);
        }
        if (kb < 4) {
            const __half* Wl = g_wl;         // kk == 0
#pragma unroll
            for (int q = 0; q < 2; q++) {
                int i = tid + 256 * q;       // Bl: 512 x 16B
                int r = i >> 2, cg = i & 3;
                cp_async16(Bl + r * HS + cg * 8, Wl + r * 128 + ks0 + cg * 8);
            }
        }
        cp_commit();
    };

    load_stage(0, 0);

    for (int kb = 0; kb < 20; kb++) {
        int s = kb & 1;
        if (kb < 19) load_stage(s ^ 1, kb + 1);
        if (kb < 19) cp_wait<1>(); else cp_wait<0>();
        __syncthreads();

        const __half* Ar  = shh + s * STAGE_H;
        const __half* Bhr = Ar + A_ST;
        const __half* Blr = Bhr + B_ST;
        bool comp = (kb < 4);

#pragma unroll
        for (int kc = 0; kc < 2; kc++) {
            int k0 = kc * 16;
            uint32_t a[2][4];
#pragma unroll
            for (int mt = 0; mt < 2; mt++) {
                int rb = m_warp + mt * 16;
                a[mt][0] = *(const uint32_t*)(Ar + (rb + g)     * HS + k0 + 2 * tig);
                a[mt][1] = *(const uint32_t*)(Ar + (rb + g + 8) * HS + k0 + 2 * tig);
                a[mt][2] = *(const uint32_t*)(Ar + (rb + g)     * HS + k0 + 2 * tig + 8);
                a[mt][3] = *(const uint32_t*)(Ar + (rb + g + 8) * HS + k0 + 2 * tig + 8);
            }
#pragma unroll
            for (int nt = 0; nt < 8; nt++) {
                int nb = n_warp + nt * 8;
                uint32_t bh[2];
                bh[0] = *(const uint32_t*)(Bhr + (nb + g) * HS + k0 + 2 * tig);
                bh[1] = *(const uint32_t*)(Bhr + (nb + g) * HS + k0 + 2 * tig + 8);
                if (comp) {
                    uint32_t bl[2];
                    bl[0] = *(const uint32_t*)(Blr + (nb + g) * HS + k0 + 2 * tig);
                    bl[1] = *(const uint32_t*)(Blr + (nb + g) * HS + k0 + 2 * tig + 8);
#pragma unroll
                    for (int mt = 0; mt < 2; mt++)
                        mma_f16(acc[mt][nt], a[mt], bl);   // A * W_lo (k=0 only)
                }
#pragma unroll
                for (int mt = 0; mt < 2; mt++)
                    mma_f16(acc[mt][nt], a[mt], bh);       // A * W_hi
            }
        }
        __syncthreads();   // stage s consumed; safe to refill next iteration
    }

    // ---- epilogue: transpose via smem, add bias, write out ----
    // epi[o][m'] with m' = v_local + 32*b  (v_local = m_local>>2, b = m_local&3)
    float* epi = (float*)shh;   // 128 x EPI_STRIDE floats = 67584 B
    __syncthreads();

#pragma unroll
    for (int mt = 0; mt < 2; mt++) {
#pragma unroll
        for (int nt = 0; nt < 8; nt++) {
#pragma unroll
            for (int j = 0; j < 4; j++) {
                int c = n_warp + nt * 8 + 2 * tig + (j & 1);
                int m_loc = m_warp + mt * 16 + g + 8 * (j >> 1);
                int mp = (m_loc >> 2) + 32 * (m_loc & 3);
                epi[c * EPI_STRIDE + mp] = acc[mt][nt][j];
            }
        }
    }
    __syncthreads();

    int v0 = (int)(row0 >> 2);   // block's first node
    for (int p = warp; p < 512; p += 8) {
        int b = p >> 7, o = p & 127;
        float bv = bias[o];
        int vg = v0 + lane;
        float val = epi[o * EPI_STRIDE + 32 * b + lane] + bv;
        if (vg < V_NODES)
            out[(size_t)(b * 128 + o) * V_NODES + vg] = val;
    }
}

// ---------------- launch ----------------
extern "C" void kernel_launch(void* const* d_in, const int* in_sizes, int n_in,
                              void* d_out, int out_size) {
    const float* x        = (const float*)d_in[0];
    const float* lap_vals = (const float*)d_in[1];
    const float* weight   = (const float*)d_in[2];
    const float* bias     = (const float*)d_in[3];
    const int*   rows     = (const int*)d_in[4];
    const int*   cols     = (const int*)d_in[5];
    int E = in_sizes[1];
    float* out = (float*)d_out;

    cudaFuncSetAttribute(gemm3_k, cudaFuncAttributeMaxDynamicSharedMemorySize, GEMM_SMEM);

    dim3 tb(32, 32);
    dim3 tg((V_NODES + 31) / 32, FEAT / 32);

    // layout in: P0 fp16 (also zeroes g_cnt for count_k)
    transpose_in<<<tg, tb>>>(x);

    // combined weights (fp16 hi/lo, transposed)
    wcomb_k<<<(CIN * COUT + 255) / 256, 256>>>(weight);

    // CSR build
    count_k<<<1024, 256>>>(rows, E);
    scan1_k<<<NB_SCAN, 256>>>();
    scan2_k<<<1, 256>>>();
    scan3_k<<<NB_SCAN, 256>>>();      // also zeroes g_cnt for scatter
    scatter_k<<<1024, 256>>>(rows, cols, lap_vals, E);

    // pure powers P1..P4 (fp16 storage, fp32 accumulate)
    dim3 spgrid((V_NODES * 32 + 255) / 256, NCHUNK);
    spmm_k<<<spgrid, 256>>>(1, 0);   // P1 = L P0
    spmm_k<<<spgrid, 256>>>(2, 1);   // P2 = L P1
    spmm_k<<<spgrid, 256>>>(3, 2);   // P3 = L P2
    spmm_k<<<spgrid, 256>>>(4, 3);   // P4 = L P3

    // fused projection + transpose + bias
    gemm3_k<<<(MROWS + 127) / 128, 256, GEMM_SMEM>>>(out, bias);
}

// round 12
// speedup vs baseline: 2.8086x; 1.0871x over previous
#include <cuda_runtime.h>
#include <cuda_fp16.h>
#include <cstdint>

#define V_NODES 50000
#define FEAT    512          // B * Cin
#define CIN     128
#define COUT    128
#define BATCH   4
#define MROWS   (V_NODES * BATCH)   // 200000
#define MAXE    800000
#define KORD    5
#define NB_SCAN ((V_NODES + 255) / 256)   // 196
#define NCHUNK  2                          // 2 x 256-feature slices

// ---------------- static device scratch (no allocations allowed) ----------------
__device__ __half g_h0[(size_t)V_NODES * FEAT];     // P0..P4 fp16
__device__ __half g_h1[(size_t)V_NODES * FEAT];
__device__ __half g_h2[(size_t)V_NODES * FEAT];
__device__ __half g_h3[(size_t)V_NODES * FEAT];
__device__ __half g_h4[(size_t)V_NODES * FEAT];
__device__ __half g_wh[KORD * CIN * COUT];          // combined weights fp16 (layout [k][o][i])
__device__ int    g_rp[V_NODES + 1];
__device__ int    g_cnt[V_NODES];
__device__ int    g_bsum[NB_SCAN];
__device__ int    g_boff[NB_SCAN];
__device__ int    g_ccol[MAXE];
__device__ float  g_cval[MAXE];

__device__ __forceinline__ __half* pick_h(int i) {
    switch (i) {
        case 0: return g_h0;
        case 1: return g_h1;
        case 2: return g_h2;
        case 3: return g_h3;
        default: return g_h4;
    }
}

// ---------------- fp16 mma ----------------
__device__ __forceinline__ void mma_f16(float* d, const uint32_t* a, const uint32_t* b) {
    asm volatile(
        "mma.sync.aligned.m16n8k16.row.col.f32.f16.f16.f32 "
        "{%0,%1,%2,%3}, {%4,%5,%6,%7}, {%8,%9}, {%0,%1,%2,%3};"
        : "+f"(d[0]), "+f"(d[1]), "+f"(d[2]), "+f"(d[3])
        : "r"(a[0]), "r"(a[1]), "r"(a[2]), "r"(a[3]), "r"(b[0]), "r"(b[1]));
}

// ---------------- cp.async helpers ----------------
__device__ __forceinline__ void cp_async16(void* smem_dst, const void* gmem_src) {
    uint32_t s = (uint32_t)__cvta_generic_to_shared(smem_dst);
    asm volatile("cp.async.cg.shared.global [%0], [%1], 16;" :: "r"(s), "l"(gmem_src));
}
__device__ __forceinline__ void cp_commit() {
    asm volatile("cp.async.commit_group;");
}
template <int N>
__device__ __forceinline__ void cp_wait() {
    asm volatile("cp.async.wait_group %0;" :: "n"(N));
}

// ---------------- transpose: x (512, V) -> g_h0 (V, 512) fp16 ----------------
__global__ void transpose_in(const float* __restrict__ x) {
    __shared__ float tile[32][33];
    int v = blockIdx.x * 32 + threadIdx.x;
    int f = blockIdx.y * 32 + threadIdx.y;
    if (v < V_NODES)
        tile[threadIdx.y][threadIdx.x] = x[(size_t)f * V_NODES + v];
    __syncthreads();
    int vo = blockIdx.x * 32 + threadIdx.y;
    int fo = blockIdx.y * 32 + threadIdx.x;
    if (vo < V_NODES)
        g_h0[(size_t)vo * FEAT + fo] = __float2half(tile[threadIdx.x][threadIdx.y]);
}

// ---------------- combined weights (fp16, [k][o][i]) + zero g_cnt ----------------
// T0..T4 = {P0, P1, 2P2-P0, 4P3-3P1, 8P4-8P2+P0};  out = sum_k Tk Wk = sum_j Pj W~j
// grid NB_SCAN x 256 covers both V_NODES (zeroing) and CIN*COUT (weights).
__global__ void wcomb_k(const float* __restrict__ w) {
    int gid = blockIdx.x * 256 + threadIdx.x;
    if (gid < V_NODES) g_cnt[gid] = 0;
    if (gid >= CIN * COUT) return;
    const int S = CIN * COUT;
    float w0 = w[gid], w1 = w[gid + S], w2 = w[gid + 2 * S], w3 = w[gid + 3 * S], w4 = w[gid + 4 * S];
    float wt[KORD];
    wt[0] = w0 - w2 + w4;
    wt[1] = w1 - 3.f * w3;
    wt[2] = 2.f * w2 - 8.f * w4;
    wt[3] = 4.f * w3;
    wt[4] = 8.f * w4;
    int iin = gid >> 7, o = gid & 127;
#pragma unroll
    for (int j = 0; j < KORD; j++)
        g_wh[j * S + o * 128 + iin] = __float2half(wt[j]);
}

// ---------------- CSR build ----------------
__global__ void count_k(const int* __restrict__ rows, int E) {
    int e = blockIdx.x * blockDim.x + threadIdx.x;
    int stride = gridDim.x * blockDim.x;
    for (; e < E; e += stride) atomicAdd(&g_cnt[rows[e]], 1);
}

__global__ void scan1_k() {
    __shared__ int sh[256];
    int t = threadIdx.x;
    int i = blockIdx.x * 256 + t;
    int c = (i < V_NODES) ? g_cnt[i] : 0;
    sh[t] = c;
    __syncthreads();
    for (int off = 1; off < 256; off <<= 1) {
        int v = sh[t];
        int add = (t >= off) ? sh[t - off] : 0;
        __syncthreads();
        sh[t] = v + add;
        __syncthreads();
    }
    if (t == 255) g_bsum[blockIdx.x] = sh[255];
}

__global__ void scan2_k() {
    __shared__ int sh[256];
    int t = threadIdx.x;
    int v0 = (t < NB_SCAN) ? g_bsum[t] : 0;
    sh[t] = v0;
    __syncthreads();
    for (int off = 1; off < 256; off <<= 1) {
        int v = sh[t];
        int add = (t >= off) ? sh[t - off] : 0;
        __syncthreads();
        sh[t] = v + add;
        __syncthreads();
    }
    if (t < NB_SCAN) g_boff[t] = (t == 0) ? 0 : sh[t - 1];
    if (t == NB_SCAN - 1) g_rp[V_NODES] = sh[t];
}

// expand + zero g_cnt in-place (scatter needs cnt=0 next)
__global__ void scan3_k() {
    __shared__ int sh[256];
    int t = threadIdx.x;
    int i = blockIdx.x * 256 + t;
    int c = (i < V_NODES) ? g_cnt[i] : 0;
    sh[t] = c;
    __syncthreads();
    for (int off = 1; off < 256; off <<= 1) {
        int v = sh[t];
        int add = (t >= off) ? sh[t - off] : 0;
        __syncthreads();
        sh[t] = v + add;
        __syncthreads();
    }
    if (i < V_NODES) {
        g_rp[i] = g_boff[blockIdx.x] + sh[t] - c;
        g_cnt[i] = 0;
    }
}

__global__ void scatter_k(const int* __restrict__ rows, const int* __restrict__ cols,
                          const float* __restrict__ vals, int E) {
    int e = blockIdx.x * blockDim.x + threadIdx.x;
    int stride = gridDim.x * blockDim.x;
    for (; e < E; e += stride) {
        int r = rows[e];
        int p = g_rp[r] + atomicAdd(&g_cnt[r], 1);
        g_ccol[p] = cols[e];
        g_cval[p] = vals[e];
    }
}

// ---------------- SpMM (fp16 in/out, fp32 accumulate) ----------------
// y[v, chunk*256 : +256] = sum_e val * x[col, slice].  One warp per (row, chunk):
// lane covers 8 features (uint4 = 16B); 32-edge coalesced prefetch + shuffle
// broadcast -> independent 512B gathers in flight.
__global__ void spmm_k(int yi, int xi) {
    int w = (blockIdx.x * blockDim.x + threadIdx.x) >> 5;
    if (w >= V_NODES) return;
    int lane = threadIdx.x & 31;

    const uint4* __restrict__ x4 = (const uint4*)pick_h(xi);
    uint4* __restrict__ y4 = (uint4*)pick_h(yi);
    int cbase = blockIdx.y * 32 + lane;   // uint4 offset within 64-uint4 row

    float acc[8];
#pragma unroll
    for (int q = 0; q < 8; q++) acc[q] = 0.f;

    int p0 = g_rp[w], p1 = g_rp[w + 1];
    for (int pb = p0; pb < p1; pb += 32) {
        int pc = pb + lane;
        int   c   = 0;
        float val = 0.f;
        if (pc < p1) { c = g_ccol[pc]; val = g_cval[pc]; }
        int n = p1 - pb; if (n > 32) n = 32;
#pragma unroll 4
        for (int j = 0; j < n; j++) {
            int   cj = __shfl_sync(0xffffffffu, c, j);
            float vj = __shfl_sync(0xffffffffu, val, j);
            uint4 raw = x4[(size_t)cj * 64 + cbase];
            const __half2* h2 = (const __half2*)&raw;
#pragma unroll
            for (int q = 0; q < 4; q++) {
                float2 f = __half22float2(h2[q]);
                acc[2 * q]     += vj * f.x;
                acc[2 * q + 1] += vj * f.y;
            }
        }
    }

    uint4 outv;
    __half2* oh = (__half2*)&outv;
#pragma unroll
    for (int q = 0; q < 4; q++) oh[q] = __floats2half2_rn(acc[2 * q], acc[2 * q + 1]);
    y4[(size_t)w * 64 + cbase] = outv;
}

// ---------------- fused fp16-MMA GEMM + epilogue: out = ([P0..P4] @ W~)^T + bias ----
// A fp16 (exact), W~ fp16 (quantization ~2.4e-4, within budget). 32 MMAs/stage.
#define HS       40                         // half stride (20 words: conflict-free)
#define A_ST     (128 * HS)                 // 5120 halfs = 10240 B
#define B_ST     (128 * HS)
#define STAGE_H  (A_ST + B_ST)              // 10240 halfs = 20480 B
#define GEMM_SMEM 67584                     // max(2*20480, epi 128*132*4)
#define EPI_STRIDE 132

__global__ __launch_bounds__(256, 2) void gemm3_k(float* __restrict__ out,
                                                  const float* __restrict__ bias) {
    extern __shared__ __align__(16) __half shh[];
    int tid = threadIdx.x;
    int warp = tid >> 5, lane = tid & 31;
    int g = lane >> 2, tig = lane & 3;
    int wm = warp >> 1, wn = warp & 1;       // 4 x 2 warp grid
    int m_warp = wm * 32, n_warp = wn * 64;
    size_t row0 = (size_t)blockIdx.x * 128;

    float acc[2][8][4];
#pragma unroll
    for (int mt = 0; mt < 2; mt++)
#pragma unroll
        for (int nt = 0; nt < 8; nt++)
#pragma unroll
            for (int j = 0; j < 4; j++) acc[mt][nt][j] = 0.f;

    // ---- stage loader (cp.async): A 512 + B 512 chunks of 16B ----
    auto load_stage = [&](int s, int kb) {
        int kk  = kb >> 2;
        int ks0 = (kb & 3) * 32;
        const __half* A  = pick_h(kk);
        const __half* Wh = g_wh + kk * (CIN * COUT);
        __half* As = shh + s * STAGE_H;
        __half* Bh = As + A_ST;
#pragma unroll
        for (int q = 0; q < 2; q++) {
            int i = tid + 256 * q;           // A: 512 x 16B (row = 4 chunks of 8 halfs)
            int r = i >> 2, cg = i & 3;
            size_t ar = row0 + r;
            if (ar >= MROWS) ar = MROWS - 1;
            cp_async16(As + r * HS + cg * 8, A + ar * 128 + ks0 + cg * 8);
        }
#pragma unroll
        for (int q = 0; q < 2; q++) {
            int i = tid + 256 * q;           // B: 512 x 16B
            int r = i >> 2, cg = i & 3;
            cp_async16(Bh + r * HS + cg * 8, Wh + r * 128 + ks0 + cg * 8);
        }
        cp_commit();
    };

    load_stage(0, 0);

    for (int kb = 0; kb < 20; kb++) {
        int s = kb & 1;
        if (kb < 19) load_stage(s ^ 1, kb + 1);
        if (kb < 19) cp_wait<1>(); else cp_wait<0>();
        __syncthreads();

        const __half* Ar  = shh + s * STAGE_H;
        const __half* Bhr = Ar + A_ST;

#pragma unroll
        for (int kc = 0; kc < 2; kc++) {
            int k0 = kc * 16;
            uint32_t a[2][4];
#pragma unroll
            for (int mt = 0; mt < 2; mt++) {
                int rb = m_warp + mt * 16;
                a[mt][0] = *(const uint32_t*)(Ar + (rb + g)     * HS + k0 + 2 * tig);
                a[mt][1] = *(const uint32_t*)(Ar + (rb + g + 8) * HS + k0 + 2 * tig);
                a[mt][2] = *(const uint32_t*)(Ar + (rb + g)     * HS + k0 + 2 * tig + 8);
                a[mt][3] = *(const uint32_t*)(Ar + (rb + g + 8) * HS + k0 + 2 * tig + 8);
            }
#pragma unroll
            for (int nt = 0; nt < 8; nt++) {
                int nb = n_warp + nt * 8;
                uint32_t bh[2];
                bh[0] = *(const uint32_t*)(Bhr + (nb + g) * HS + k0 + 2 * tig);
                bh[1] = *(const uint32_t*)(Bhr + (nb + g) * HS + k0 + 2 * tig + 8);
#pragma unroll
                for (int mt = 0; mt < 2; mt++)
                    mma_f16(acc[mt][nt], a[mt], bh);
            }
        }
        __syncthreads();   // stage s consumed; safe to refill next iteration
    }

    // ---- epilogue: transpose via smem, add bias, write out ----
    // epi[o][m'] with m' = v_local + 32*b  (v_local = m_local>>2, b = m_local&3)
    float* epi = (float*)shh;   // 128 x EPI_STRIDE floats = 67584 B
    __syncthreads();

#pragma unroll
    for (int mt = 0; mt < 2; mt++) {
#pragma unroll
        for (int nt = 0; nt < 8; nt++) {
#pragma unroll
            for (int j = 0; j < 4; j++) {
                int c = n_warp + nt * 8 + 2 * tig + (j & 1);
                int m_loc = m_warp + mt * 16 + g + 8 * (j >> 1);
                int mp = (m_loc >> 2) + 32 * (m_loc & 3);
                epi[c * EPI_STRIDE + mp] = acc[mt][nt][j];
            }
        }
    }
    __syncthreads();

    int v0 = (int)(row0 >> 2);   // block's first node
    for (int p = warp; p < 512; p += 8) {
        int b = p >> 7, o = p & 127;
        float bv = bias[o];
        int vg = v0 + lane;
        float val = epi[o * EPI_STRIDE + 32 * b + lane] + bv;
        if (vg < V_NODES)
            out[(size_t)(b * 128 + o) * V_NODES + vg] = val;
    }
}

// ---------------- launch ----------------
extern "C" void kernel_launch(void* const* d_in, const int* in_sizes, int n_in,
                              void* d_out, int out_size) {
    const float* x        = (const float*)d_in[0];
    const float* lap_vals = (const float*)d_in[1];
    const float* weight   = (const float*)d_in[2];
    const float* bias     = (const float*)d_in[3];
    const int*   rows     = (const int*)d_in[4];
    const int*   cols     = (const int*)d_in[5];
    int E = in_sizes[1];
    float* out = (float*)d_out;

    // one-time host-side plumbing (no device memory involved)
    static cudaStream_t s_aux = nullptr;
    static cudaEvent_t  ev_fork = nullptr, ev_join = nullptr;
    if (!s_aux) {
        cudaStreamCreateWithFlags(&s_aux, cudaStreamNonBlocking);
        cudaEventCreateWithFlags(&ev_fork, cudaEventDisableTiming);
        cudaEventCreateWithFlags(&ev_join, cudaEventDisableTiming);
        cudaFuncSetAttribute(gemm3_k, cudaFuncAttributeMaxDynamicSharedMemorySize, GEMM_SMEM);
    }

    dim3 tb(32, 32);
    dim3 tg((V_NODES + 31) / 32, FEAT / 32);

    // fork: CSR build chain on s_aux, concurrent with transpose_in on stream 0
    cudaEventRecord(ev_fork, 0);
    cudaStreamWaitEvent(s_aux, ev_fork, 0);

    wcomb_k<<<NB_SCAN, 256, 0, s_aux>>>(weight);   // weights + zero g_cnt
    count_k<<<1024, 256, 0, s_aux>>>(rows, E);
    scan1_k<<<NB_SCAN, 256, 0, s_aux>>>();
    scan2_k<<<1, 256, 0, s_aux>>>();
    scan3_k<<<NB_SCAN, 256, 0, s_aux>>>();         // also zeroes g_cnt for scatter
    scatter_k<<<1024, 256, 0, s_aux>>>(rows, cols, lap_vals, E);

    transpose_in<<<tg, tb>>>(x);                   // stream 0, overlapped

    // join
    cudaEventRecord(ev_join, s_aux);
    cudaStreamWaitEvent(0, ev_join, 0);

    // pure powers P1..P4 (fp16 storage, fp32 accumulate)
    dim3 spgrid((V_NODES * 32 + 255) / 256, NCHUNK);
    spmm_k<<<spgrid, 256>>>(1, 0);   // P1 = L P0
    spmm_k<<<spgrid, 256>>>(2, 1);   // P2 = L P1
    spmm_k<<<spgrid, 256>>>(3, 2);   // P3 = L P2
    spmm_k<<<spgrid, 256>>>(4, 3);   // P4 = L P3

    // fused projection + transpose + bias
    gemm3_k<<<(MROWS + 127) / 128, 256, GEMM_SMEM>>>(out, bias);
}